// round 11
// baseline (speedup 1.0000x reference)
#include <cuda_runtime.h>
#include <cuda_bf16.h>
#include <cstdint>

// HGAN triplet loss. Projections and score bilinear forms on HMMA
// (mma.sync m16n8k16 bf16, fp32 acc, 3-pass hi/lo split).
// Score CTA = 64n x 256m (A-operand split work amortized over full m),
// cp.async double-buffered C staging.

#define B_ 32
#define N_ 256
#define E_ 300
#define H_ 256
#define K_ 8
#define KSTEPS 19     // ceil(300/16)

// ---------------------------------------------------------------------------
// Device scratch (allocation-free per harness rules)
// ---------------------------------------------------------------------------
__device__ float    g_projT[B_][N_][H_];             // anchor proj, [n][h]
__device__ uint32_t g_Cpk[B_][2][2][256][128];       // [b][side][hi/lo][m][h/2]
__device__ uint32_t g_Wpk[2][2][KSTEPS][256][8];     // [a2h/c2h][hi/lo][ks][h][k/2]
__device__ float    g_pnum[2][B_][K_][4];
__device__ float    g_pden[2][B_][K_][4];

// ---------------------------------------------------------------------------
// Helpers
// ---------------------------------------------------------------------------
__device__ __forceinline__ uint32_t smem_u32(const void* p) {
    uint32_t a;
    asm("{ .reg .u64 t; cvta.to.shared.u64 t, %1; cvt.u32.u64 %0, t; }" : "=r"(a) : "l"(p));
    return a;
}
__device__ __forceinline__ uint32_t cvt2(float v0, float v1) {
    uint32_t r;
    asm("cvt.rn.bf16x2.f32 %0, %1, %2;" : "=r"(r) : "f"(v1), "f"(v0));
    return r;
}
__device__ __forceinline__ void split2(float v0, float v1, uint32_t& uhi, uint32_t& ulo) {
    uhi = cvt2(v0, v1);
    float f0 = __uint_as_float(uhi << 16);
    float f1 = __uint_as_float(uhi & 0xffff0000u);
    ulo = cvt2(v0 - f0, v1 - f1);
}
__device__ __forceinline__ void ldsm4(uint32_t* r, uint32_t addr) {
    asm volatile("ldmatrix.sync.aligned.m8n8.x4.shared.b16 {%0,%1,%2,%3}, [%4];"
        : "=r"(r[0]), "=r"(r[1]), "=r"(r[2]), "=r"(r[3]) : "r"(addr));
}
__device__ __forceinline__ void mma_bf16(float* d, const uint32_t* a,
                                         uint32_t b0, uint32_t b1) {
    asm volatile("mma.sync.aligned.m16n8k16.row.col.f32.bf16.bf16.f32 "
        "{%0,%1,%2,%3}, {%4,%5,%6,%7}, {%8,%9}, {%0,%1,%2,%3};"
        : "+f"(d[0]), "+f"(d[1]), "+f"(d[2]), "+f"(d[3])
        : "r"(a[0]), "r"(a[1]), "r"(a[2]), "r"(a[3]), "r"(b0), "r"(b1));
}
__device__ __forceinline__ void cp16(uint32_t dst, const void* src) {
    asm volatile("cp.async.cg.shared.global [%0], [%1], 16;" :: "r"(dst), "l"(src));
}
#define CP_COMMIT() asm volatile("cp.async.commit_group;" ::: "memory")
#define CP_WAIT(n)  asm volatile("cp.async.wait_group %0;" :: "n"(n) : "memory")

// exp via 2^(x*log2e), deg-5 minimax poly (rel err ~3e-8), FMA-pipe only.
__device__ __forceinline__ float exp_poly(float x) {
    float t = x * 1.4426950408889634f;
    float fi = rintf(t);
    float f = t - fi;
    float p = 0.00133335581f;
    p = fmaf(p, f, 0.00961804886f);
    p = fmaf(p, f, 0.0555041087f);
    p = fmaf(p, f, 0.240226507f);
    p = fmaf(p, f, 0.69314718056f);
    p = fmaf(p, f, 1.0f);
    float s = __int_as_float(((int)fi + 127) << 23);
    return p * s;
}

// ---------------------------------------------------------------------------
// W prep (unchanged)
// ---------------------------------------------------------------------------
__global__ __launch_bounds__(256)
void wprep_kernel(const float* __restrict__ Wa, const float* __restrict__ Wc) {
    const int mode = blockIdx.x & 1, ks = blockIdx.x >> 1;
    const int h = threadIdx.x;
    const float* W = mode ? Wc : Wa;
    const int e0 = ks * 16;
    float v[16];
    #pragma unroll
    for (int j = 0; j < 16; j++)
        v[j] = (e0 + j < E_) ? W[h * E_ + e0 + j] : 0.f;
    #pragma unroll
    for (int i = 0; i < 8; i++) {
        uint32_t hi, lo;
        split2(v[2 * i], v[2 * i + 1], hi, lo);
        g_Wpk[mode][0][ks][h][i] = hi;
        g_Wpk[mode][1][ks][h][i] = lo;
    }
}

// ---------------------------------------------------------------------------
// Projection on HMMA (unchanged from R9/R10)
// ---------------------------------------------------------------------------
#define PSTR 12

__global__ __launch_bounds__(256, 2)
void projmma_kernel(const float* __restrict__ Xa, const float* __restrict__ Xp,
                    const float* __restrict__ Xn,
                    const float* __restrict__ ba, const float* __restrict__ bc) {
    __shared__ uint32_t XH[64 * PSTR], XL[64 * PSTR];
    __shared__ uint32_t WH[256 * PSTR], WL[256 * PSTR];
    __shared__ float bias_s[256];

    const int tid = threadIdx.x, lane = tid & 31, w = tid >> 5;
    const int nq = blockIdx.x;
    const int mb = blockIdx.z;
    const int mode = mb >> 5, b = mb & 31;

    const float* X    = (mode == 0) ? Xa : (mode == 1 ? Xp : Xn);
    const float* bias = (mode == 0) ? ba : bc;
    const int    wsel = (mode == 0) ? 0 : 1;

    bias_s[tid] = bias[tid];

    const float* Xbase = X + ((size_t)b * N_ + nq * 64) * E_;
    const int warp_n = w & 3, warp_h = w >> 2;

    const uint32_t xhb = smem_u32(XH), xlb = smem_u32(XL);
    const uint32_t whb = smem_u32(WH), wlb = smem_u32(WL);

    const uint32_t a_off = (uint32_t)(warp_n * 16 + (lane & 15)) * 48 + ((lane >> 4) << 4);
    const uint32_t c_off = (uint32_t)((lane & 7) + ((lane >> 4) << 3)) * 48
                         + (((lane >> 3) & 1) << 4);

    const int fx_n = tid >> 2, fx_q = tid & 3;

    float acc[16][4];
    #pragma unroll
    for (int i = 0; i < 16; i++)
        #pragma unroll
        for (int j = 0; j < 4; j++) acc[i][j] = 0.f;

    for (int ks = 0; ks < KSTEPS; ks++) {
        const int e0 = ks * 16;
        __syncthreads();

        {
            float4 v = make_float4(0.f, 0.f, 0.f, 0.f);
            if (e0 + fx_q * 4 < E_)
                v = *(const float4*)(Xbase + fx_n * E_ + e0 + fx_q * 4);
            uint32_t h0, l0, h1, l1;
            split2(v.x, v.y, h0, l0);
            split2(v.z, v.w, h1, l1);
            const int o = fx_n * PSTR + fx_q * 2;
            XH[o] = h0; XH[o + 1] = h1;
            XL[o] = l0; XL[o + 1] = l1;
        }
        #pragma unroll
        for (int i = 0; i < 4; i++) {
            int idx = tid + i * 256;
            int var = idx >> 9, rem = idx & 511;
            int h = rem >> 1, half = rem & 1;
            uint4 v = *(const uint4*)&g_Wpk[wsel][var][ks][h][half * 4];
            uint32_t* dst = (var ? WL : WH) + h * PSTR + half * 4;
            *(uint4*)dst = v;
        }
        __syncthreads();

        uint32_t aH[4], aL[4];
        ldsm4(aH, xhb + a_off);
        ldsm4(aL, xlb + a_off);
        #pragma unroll
        for (int qh = 0; qh < 4; qh++) {
            const uint32_t hb = (uint32_t)(warp_h * 128 + qh * 32) * 48;
            uint32_t bh[8], bl[8];
            ldsm4(bh + 0, whb + hb + c_off);
            ldsm4(bh + 4, whb + hb + 16 * 48 + c_off);
            ldsm4(bl + 0, wlb + hb + c_off);
            ldsm4(bl + 4, wlb + hb + 16 * 48 + c_off);
            #pragma unroll
            for (int t2 = 0; t2 < 4; t2++) {
                const int ht = qh * 4 + t2;
                mma_bf16(acc[ht], aH, bh[2 * t2], bh[2 * t2 + 1]);
                mma_bf16(acc[ht], aL, bh[2 * t2], bh[2 * t2 + 1]);
                mma_bf16(acc[ht], aH, bl[2 * t2], bl[2 * t2 + 1]);
            }
        }
    }

    const int g = lane >> 2, q = lane & 3;
    const int n0 = nq * 64 + warp_n * 16 + g;
    #pragma unroll
    for (int ht = 0; ht < 16; ht++) {
        const int h = warp_h * 128 + ht * 8 + 2 * q;
        const float b0 = bias_s[h], b1 = bias_s[h + 1];
        const float x0 = acc[ht][0] + b0, x1 = acc[ht][1] + b1;
        const float x2 = acc[ht][2] + b0, x3 = acc[ht][3] + b1;
        if (mode == 0) {
            *(float2*)&g_projT[b][n0][h]     = make_float2(x0, x1);
            *(float2*)&g_projT[b][n0 + 8][h] = make_float2(x2, x3);
        } else {
            const int side = mode - 1;
            uint32_t hi, lo;
            split2(x0, x1, hi, lo);
            g_Cpk[b][side][0][n0][h >> 1] = hi;
            g_Cpk[b][side][1][n0][h >> 1] = lo;
            split2(x2, x3, hi, lo);
            g_Cpk[b][side][0][n0 + 8][h >> 1] = hi;
            g_Cpk[b][side][1][n0 + 8][h >> 1] = lo;
        }
    }
}

// ---------------------------------------------------------------------------
// Score: CTA = 64n x 256m of one (k, b, side). bx = k + 8*nh (nh 0..3).
// Warp w: n rows [nh*64 + 16*(w&3), +16), m cols [128*(w>>2), +128).
// A fragments in registers (LDG fp32 -> scale -> split), amortized over m=256.
// C staged via cp.async, double-buffered.
// ---------------------------------------------------------------------------
#define ASTR 20                       // u32 row stride (80 B)
#define CBUF_U32 (256 * ASTR)         // 5120 u32 per hi/lo buffer
#define SC_SMEM (2 * 2 * CBUF_U32 * 4 + 2048 + 64)   // 84032 B

__global__ __launch_bounds__(256, 1)
void score_kernel(const float* __restrict__ W_att, const float* __restrict__ W_fc) {
    extern __shared__ uint32_t smem[];
    float* watt_s = (float*)(smem + 4 * CBUF_U32);
    float* wfc_s  = watt_s + 256;
    float* rn     = wfc_s + 256;
    float* rd     = rn + 8;

    const int tid  = threadIdx.x;
    const int lane = tid & 31, w = tid >> 5;
    const int k  = blockIdx.x & 7;
    const int nh = blockIdx.x >> 3;
    const int b = blockIdx.y, side = blockIdx.z;

    watt_s[tid] = W_att[k * H_ + tid];
    wfc_s [tid] = W_fc [k * H_ + tid];

    const float*    At = &g_projT[b][0][0];
    const uint32_t* Cp = &g_Cpk[b][side][0][0][0];
    const uint32_t sbase = smem_u32(smem);

    const int g = lane >> 2, t = lane & 3;
    const int n_r0 = nh * 64 + 16 * (w & 3) + g;
    const int n_r1 = n_r0 + 8;
    const int warp_m = w >> 2;
    const uint32_t c_off = (uint32_t)((lane & 7) + ((lane >> 4) << 3)) * (ASTR * 4)
                         + (((lane >> 3) & 1) << 4);

    // prefetch indices: idx = tid + i*256 (i<8); var|m|q
    // src contiguous per 4 threads (q fastest) -> coalesced 64B
    float accS[4][4][4], accF[4][4][4];
    #pragma unroll
    for (int mh = 0; mh < 4; mh++)
        #pragma unroll
        for (int gg = 0; gg < 4; gg++)
            #pragma unroll
            for (int r = 0; r < 4; r++) { accS[mh][gg][r] = 0.f; accF[mh][gg][r] = 0.f; }

    // ---- prefetch chunk 0 into buffer 0
    #pragma unroll
    for (int i = 0; i < 8; i++) {
        int idx = tid + i * 256;
        int var = idx >> 10, rem = idx & 1023;
        int m = rem >> 2, q = rem & 3;
        const uint32_t* src = Cp + (size_t)var * 256 * 128 + (size_t)m * 128 + q * 4;
        uint32_t dst = sbase + (uint32_t)(var * CBUF_U32 + m * ASTR + q * 4) * 4;
        cp16(dst, src);
    }
    CP_COMMIT();

    for (int hc = 0; hc < 8; hc++) {
        const uint32_t buf  = (uint32_t)(hc & 1);
        if (hc < 7) {
            const uint32_t nbuf = buf ^ 1;
            #pragma unroll
            for (int i = 0; i < 8; i++) {
                int idx = tid + i * 256;
                int var = idx >> 10, rem = idx & 1023;
                int m = rem >> 2, q = rem & 3;
                const uint32_t* src = Cp + (size_t)var * 256 * 128 + (size_t)m * 128
                                    + (hc + 1) * 16 + q * 4;
                uint32_t dst = sbase + (uint32_t)(nbuf * 2 * CBUF_U32 + var * CBUF_U32
                                                  + m * ASTR + q * 4) * 4;
                cp16(dst, src);
            }
            CP_COMMIT();
            CP_WAIT(1);
        } else {
            CP_WAIT(0);
        }
        __syncthreads();   // chunk hc data visible to all; prev buffer safe to reuse

        const uint32_t cHb = sbase + buf * 2 * CBUF_U32 * 4;
        const uint32_t cLb = cHb + CBUF_U32 * 4;
        const int h0 = hc * 32;

        #pragma unroll
        for (int ks = 0; ks < 2; ks++) {
            const int h0k = h0 + ks * 16;
            float2 v00 = *(const float2*)(At + n_r0 * H_ + h0k + 2 * t);
            float2 v10 = *(const float2*)(At + n_r1 * H_ + h0k + 2 * t);
            float2 v01 = *(const float2*)(At + n_r0 * H_ + h0k + 2 * t + 8);
            float2 v11 = *(const float2*)(At + n_r1 * H_ + h0k + 2 * t + 8);
            float2 wa0 = *(const float2*)(watt_s + h0k + 2 * t);
            float2 wa1 = *(const float2*)(watt_s + h0k + 2 * t + 8);
            float2 wf0 = *(const float2*)(wfc_s  + h0k + 2 * t);
            float2 wf1 = *(const float2*)(wfc_s  + h0k + 2 * t + 8);

            uint32_t aSh[4], aSl[4], aFh[4], aFl[4];
            split2(wa0.x * v00.x, wa0.y * v00.y, aSh[0], aSl[0]);
            split2(wa0.x * v10.x, wa0.y * v10.y, aSh[1], aSl[1]);
            split2(wa1.x * v01.x, wa1.y * v01.y, aSh[2], aSl[2]);
            split2(wa1.x * v11.x, wa1.y * v11.y, aSh[3], aSl[3]);
            split2(wf0.x * v00.x, wf0.y * v00.y, aFh[0], aFl[0]);
            split2(wf0.x * v10.x, wf0.y * v10.y, aFh[1], aFl[1]);
            split2(wf1.x * v01.x, wf1.y * v01.y, aFh[2], aFl[2]);
            split2(wf1.x * v11.x, wf1.y * v11.y, aFh[3], aFl[3]);

            const uint32_t hkb = (uint32_t)(ks * 32);
            #pragma unroll
            for (int mh = 0; mh < 4; mh++) {
                const uint32_t mrow = (uint32_t)(warp_m * 128 + mh * 32) * (ASTR * 4);
                uint32_t c[8];
                ldsm4(c + 0, cHb + mrow + c_off + hkb);
                ldsm4(c + 4, cHb + mrow + 16 * ASTR * 4 + c_off + hkb);
                #pragma unroll
                for (int gg = 0; gg < 4; gg++) {
                    mma_bf16(accS[mh][gg], aSh, c[2*gg], c[2*gg+1]);
                    mma_bf16(accS[mh][gg], aSl, c[2*gg], c[2*gg+1]);
                    mma_bf16(accF[mh][gg], aFh, c[2*gg], c[2*gg+1]);
                    mma_bf16(accF[mh][gg], aFl, c[2*gg], c[2*gg+1]);
                }
                ldsm4(c + 0, cLb + mrow + c_off + hkb);
                ldsm4(c + 4, cLb + mrow + 16 * ASTR * 4 + c_off + hkb);
                #pragma unroll
                for (int gg = 0; gg < 4; gg++) {
                    mma_bf16(accS[mh][gg], aSh, c[2*gg], c[2*gg+1]);
                    mma_bf16(accF[mh][gg], aFh, c[2*gg], c[2*gg+1]);
                }
            }
        }
        __syncthreads();   // all warps done with buffer `buf` before it is refilled
    }

    // ---- epilogue: hybrid exp (even -> MUFU EX2, odd -> FMA-pipe poly)
    float num = 0.f, den = 0.f;
    #pragma unroll
    for (int mh = 0; mh < 4; mh++)
        #pragma unroll
        for (int gg = 0; gg < 4; gg++)
            #pragma unroll
            for (int r = 0; r < 4; r++) {
                float S = accS[mh][gg][r];
                float e = (r & 1) ? exp_poly(S) : __expf(S);
                den += e;
                num = fmaf(e, accF[mh][gg][r], num);
            }

    #pragma unroll
    for (int o = 16; o; o >>= 1) {
        num += __shfl_down_sync(0xffffffffu, num, o);
        den += __shfl_down_sync(0xffffffffu, den, o);
    }
    if (lane == 0) { rn[w] = num; rd[w] = den; }
    __syncthreads();
    if (tid == 0) {
        float sn = 0.f, sd = 0.f;
        #pragma unroll
        for (int q = 0; q < 8; q++) { sn += rn[q]; sd += rd[q]; }
        g_pnum[side][b][k][nh] = sn;
        g_pden[side][b][k][nh] = sd;
    }
}

// ---------------------------------------------------------------------------
// Finalize: loss = mean_b relu(score_n - score_p + margin). 256 threads.
// ---------------------------------------------------------------------------
__global__ void finalize_kernel(float* __restrict__ out) {
    __shared__ float sc[8][32];
    const int lane = threadIdx.x & 31;   // = b
    const int w    = threadIdx.x >> 5;   // 8 groups x 2 (side,k) pairs
    float s = 0.f;
    #pragma unroll
    for (int pi = 0; pi < 2; pi++) {
        int p = w * 2 + pi;
        int side = p >> 3, k = p & 7;
        float n = 0.f, d = 0.f;
        #pragma unroll
        for (int q = 0; q < 4; q++) {
            n += g_pnum[side][lane][k][q];
            d += g_pden[side][lane][k][q];
        }
        float v = n / d;
        s += side ? v : -v;
    }
    sc[w][lane] = s;
    __syncthreads();
    if (w == 0) {
        float tot = 0.f;
        #pragma unroll
        for (int ww = 0; ww < 8; ww++) tot += sc[ww][lane];
        float v = fmaxf(tot + 0.2f, 0.f);
        #pragma unroll
        for (int o = 16; o; o >>= 1) v += __shfl_down_sync(0xffffffffu, v, o);
        if (lane == 0) out[0] = v * (1.0f / B_);
    }
}

// ---------------------------------------------------------------------------
extern "C" void kernel_launch(void* const* d_in, const int* in_sizes, int n_in,
                              void* d_out, int out_size) {
    const float* he_anchor = (const float*)d_in[0];
    const float* he_pos    = (const float*)d_in[1];
    const float* he_neg    = (const float*)d_in[2];
    const float* W_a2h     = (const float*)d_in[3];
    const float* b_a2h     = (const float*)d_in[4];
    const float* W_c2h     = (const float*)d_in[5];
    const float* b_c2h     = (const float*)d_in[6];
    const float* W_att     = (const float*)d_in[7];
    // d_in[8] = b_att : cancels in softmax
    const float* W_fc      = (const float*)d_in[9];
    // d_in[10] = b_fc : cancels in score difference

    static int smem_set = 0;
    if (!smem_set) {
        cudaFuncSetAttribute(score_kernel,
                             cudaFuncAttributeMaxDynamicSharedMemorySize, SC_SMEM);
        smem_set = 1;
    }

    wprep_kernel<<<2 * KSTEPS, 256>>>(W_a2h, W_c2h);

    projmma_kernel<<<dim3(4, 1, 96), 256>>>(he_anchor, he_pos, he_neg,
                                            b_a2h, b_c2h);

    score_kernel<<<dim3(32, B_, 2), 256, SC_SMEM>>>(W_att, W_fc);

    finalize_kernel<<<1, 256>>>((float*)d_out);
}

// round 12
// speedup vs baseline: 1.1088x; 1.1088x over previous
#include <cuda_runtime.h>
#include <cuda_bf16.h>
#include <cstdint>

// HGAN triplet loss. Projections and score bilinear forms on HMMA
// (mma.sync m16n8k16 bf16, fp32 acc, 3-pass hi/lo split).
// Score CTA = 128n x 64m (R10 proven config, 2 CTAs/SM) with cp.async
// double-buffered C staging.

#define B_ 32
#define N_ 256
#define E_ 300
#define H_ 256
#define K_ 8
#define KSTEPS 19     // ceil(300/16)

// ---------------------------------------------------------------------------
// Device scratch (allocation-free per harness rules)
// ---------------------------------------------------------------------------
__device__ float    g_projT[B_][N_][H_];             // anchor proj, [n][h]
__device__ uint32_t g_Cpk[B_][2][2][256][128];       // [b][side][hi/lo][m][h/2]
__device__ uint32_t g_Wpk[2][2][KSTEPS][256][8];     // [a2h/c2h][hi/lo][ks][h][k/2]
__device__ float    g_pnum[2][B_][K_][8];
__device__ float    g_pden[2][B_][K_][8];

// ---------------------------------------------------------------------------
// Helpers
// ---------------------------------------------------------------------------
__device__ __forceinline__ uint32_t smem_u32(const void* p) {
    uint32_t a;
    asm("{ .reg .u64 t; cvta.to.shared.u64 t, %1; cvt.u32.u64 %0, t; }" : "=r"(a) : "l"(p));
    return a;
}
__device__ __forceinline__ uint32_t cvt2(float v0, float v1) {
    uint32_t r;
    asm("cvt.rn.bf16x2.f32 %0, %1, %2;" : "=r"(r) : "f"(v1), "f"(v0));
    return r;
}
__device__ __forceinline__ void split2(float v0, float v1, uint32_t& uhi, uint32_t& ulo) {
    uhi = cvt2(v0, v1);
    float f0 = __uint_as_float(uhi << 16);
    float f1 = __uint_as_float(uhi & 0xffff0000u);
    ulo = cvt2(v0 - f0, v1 - f1);
}
__device__ __forceinline__ void ldsm4(uint32_t* r, uint32_t addr) {
    asm volatile("ldmatrix.sync.aligned.m8n8.x4.shared.b16 {%0,%1,%2,%3}, [%4];"
        : "=r"(r[0]), "=r"(r[1]), "=r"(r[2]), "=r"(r[3]) : "r"(addr));
}
__device__ __forceinline__ void mma_bf16(float* d, const uint32_t* a,
                                         uint32_t b0, uint32_t b1) {
    asm volatile("mma.sync.aligned.m16n8k16.row.col.f32.bf16.bf16.f32 "
        "{%0,%1,%2,%3}, {%4,%5,%6,%7}, {%8,%9}, {%0,%1,%2,%3};"
        : "+f"(d[0]), "+f"(d[1]), "+f"(d[2]), "+f"(d[3])
        : "r"(a[0]), "r"(a[1]), "r"(a[2]), "r"(a[3]), "r"(b0), "r"(b1));
}
__device__ __forceinline__ void cp16(uint32_t dst, const void* src) {
    asm volatile("cp.async.cg.shared.global [%0], [%1], 16;" :: "r"(dst), "l"(src));
}
#define CP_COMMIT() asm volatile("cp.async.commit_group;" ::: "memory")
#define CP_WAIT(n)  asm volatile("cp.async.wait_group %0;" :: "n"(n) : "memory")

// exp via 2^(x*log2e), deg-5 minimax poly (rel err ~3e-8), FMA-pipe only.
__device__ __forceinline__ float exp_poly(float x) {
    float t = x * 1.4426950408889634f;
    float fi = rintf(t);
    float f = t - fi;
    float p = 0.00133335581f;
    p = fmaf(p, f, 0.00961804886f);
    p = fmaf(p, f, 0.0555041087f);
    p = fmaf(p, f, 0.240226507f);
    p = fmaf(p, f, 0.69314718056f);
    p = fmaf(p, f, 1.0f);
    float s = __int_as_float(((int)fi + 127) << 23);
    return p * s;
}

// ---------------------------------------------------------------------------
// W prep (unchanged)
// ---------------------------------------------------------------------------
__global__ __launch_bounds__(256)
void wprep_kernel(const float* __restrict__ Wa, const float* __restrict__ Wc) {
    const int mode = blockIdx.x & 1, ks = blockIdx.x >> 1;
    const int h = threadIdx.x;
    const float* W = mode ? Wc : Wa;
    const int e0 = ks * 16;
    float v[16];
    #pragma unroll
    for (int j = 0; j < 16; j++)
        v[j] = (e0 + j < E_) ? W[h * E_ + e0 + j] : 0.f;
    #pragma unroll
    for (int i = 0; i < 8; i++) {
        uint32_t hi, lo;
        split2(v[2 * i], v[2 * i + 1], hi, lo);
        g_Wpk[mode][0][ks][h][i] = hi;
        g_Wpk[mode][1][ks][h][i] = lo;
    }
}

// ---------------------------------------------------------------------------
// Projection on HMMA (unchanged from R9/R10)
// ---------------------------------------------------------------------------
#define PSTR 12

__global__ __launch_bounds__(256, 2)
void projmma_kernel(const float* __restrict__ Xa, const float* __restrict__ Xp,
                    const float* __restrict__ Xn,
                    const float* __restrict__ ba, const float* __restrict__ bc) {
    __shared__ uint32_t XH[64 * PSTR], XL[64 * PSTR];
    __shared__ uint32_t WH[256 * PSTR], WL[256 * PSTR];
    __shared__ float bias_s[256];

    const int tid = threadIdx.x, lane = tid & 31, w = tid >> 5;
    const int nq = blockIdx.x;
    const int mb = blockIdx.z;
    const int mode = mb >> 5, b = mb & 31;

    const float* X    = (mode == 0) ? Xa : (mode == 1 ? Xp : Xn);
    const float* bias = (mode == 0) ? ba : bc;
    const int    wsel = (mode == 0) ? 0 : 1;

    bias_s[tid] = bias[tid];

    const float* Xbase = X + ((size_t)b * N_ + nq * 64) * E_;
    const int warp_n = w & 3, warp_h = w >> 2;

    const uint32_t xhb = smem_u32(XH), xlb = smem_u32(XL);
    const uint32_t whb = smem_u32(WH), wlb = smem_u32(WL);

    const uint32_t a_off = (uint32_t)(warp_n * 16 + (lane & 15)) * 48 + ((lane >> 4) << 4);
    const uint32_t c_off = (uint32_t)((lane & 7) + ((lane >> 4) << 3)) * 48
                         + (((lane >> 3) & 1) << 4);

    const int fx_n = tid >> 2, fx_q = tid & 3;

    float acc[16][4];
    #pragma unroll
    for (int i = 0; i < 16; i++)
        #pragma unroll
        for (int j = 0; j < 4; j++) acc[i][j] = 0.f;

    for (int ks = 0; ks < KSTEPS; ks++) {
        const int e0 = ks * 16;
        __syncthreads();

        {
            float4 v = make_float4(0.f, 0.f, 0.f, 0.f);
            if (e0 + fx_q * 4 < E_)
                v = *(const float4*)(Xbase + fx_n * E_ + e0 + fx_q * 4);
            uint32_t h0, l0, h1, l1;
            split2(v.x, v.y, h0, l0);
            split2(v.z, v.w, h1, l1);
            const int o = fx_n * PSTR + fx_q * 2;
            XH[o] = h0; XH[o + 1] = h1;
            XL[o] = l0; XL[o + 1] = l1;
        }
        #pragma unroll
        for (int i = 0; i < 4; i++) {
            int idx = tid + i * 256;
            int var = idx >> 9, rem = idx & 511;
            int h = rem >> 1, half = rem & 1;
            uint4 v = *(const uint4*)&g_Wpk[wsel][var][ks][h][half * 4];
            uint32_t* dst = (var ? WL : WH) + h * PSTR + half * 4;
            *(uint4*)dst = v;
        }
        __syncthreads();

        uint32_t aH[4], aL[4];
        ldsm4(aH, xhb + a_off);
        ldsm4(aL, xlb + a_off);
        #pragma unroll
        for (int qh = 0; qh < 4; qh++) {
            const uint32_t hb = (uint32_t)(warp_h * 128 + qh * 32) * 48;
            uint32_t bh[8], bl[8];
            ldsm4(bh + 0, whb + hb + c_off);
            ldsm4(bh + 4, whb + hb + 16 * 48 + c_off);
            ldsm4(bl + 0, wlb + hb + c_off);
            ldsm4(bl + 4, wlb + hb + 16 * 48 + c_off);
            #pragma unroll
            for (int t2 = 0; t2 < 4; t2++) {
                const int ht = qh * 4 + t2;
                mma_bf16(acc[ht], aH, bh[2 * t2], bh[2 * t2 + 1]);
                mma_bf16(acc[ht], aL, bh[2 * t2], bh[2 * t2 + 1]);
                mma_bf16(acc[ht], aH, bl[2 * t2], bl[2 * t2 + 1]);
            }
        }
    }

    const int g = lane >> 2, q = lane & 3;
    const int n0 = nq * 64 + warp_n * 16 + g;
    #pragma unroll
    for (int ht = 0; ht < 16; ht++) {
        const int h = warp_h * 128 + ht * 8 + 2 * q;
        const float b0 = bias_s[h], b1 = bias_s[h + 1];
        const float x0 = acc[ht][0] + b0, x1 = acc[ht][1] + b1;
        const float x2 = acc[ht][2] + b0, x3 = acc[ht][3] + b1;
        if (mode == 0) {
            *(float2*)&g_projT[b][n0][h]     = make_float2(x0, x1);
            *(float2*)&g_projT[b][n0 + 8][h] = make_float2(x2, x3);
        } else {
            const int side = mode - 1;
            uint32_t hi, lo;
            split2(x0, x1, hi, lo);
            g_Cpk[b][side][0][n0][h >> 1] = hi;
            g_Cpk[b][side][1][n0][h >> 1] = lo;
            split2(x2, x3, hi, lo);
            g_Cpk[b][side][0][n0 + 8][h >> 1] = hi;
            g_Cpk[b][side][1][n0 + 8][h >> 1] = lo;
        }
    }
}

// ---------------------------------------------------------------------------
// Score: CTA = 128n x 64m slice of one (k, b, side). bx = k + 8*mq + 32*nh.
// (R10 proven tiling, 2 CTAs/SM.) C staged via cp.async, double-buffered.
// A fragments built in registers (LDG fp32 -> scale -> hi/lo split).
// ---------------------------------------------------------------------------
#define ASTR 20                       // u32 row stride (80 B, conflict-free)
#define CB_U32 (64 * ASTR)            // 1280 u32 per hi/lo buffer

__global__ __launch_bounds__(256, 2)
void score_kernel(const float* __restrict__ W_att, const float* __restrict__ W_fc) {
    __shared__ uint32_t Cbuf[2][2][CB_U32];   // [stage][hi/lo][...]
    __shared__ float watt_s[H_], wfc_s[H_];
    __shared__ float rn[8], rd[8];

    const int tid  = threadIdx.x;
    const int lane = tid & 31, w = tid >> 5;
    const int k  = blockIdx.x & 7;
    const int mq = (blockIdx.x >> 3) & 3;
    const int nh = blockIdx.x >> 5;
    const int b = blockIdx.y, side = blockIdx.z;

    watt_s[tid] = W_att[k * H_ + tid];
    wfc_s [tid] = W_fc [k * H_ + tid];

    const float*    At = &g_projT[b][0][0];
    const uint32_t* Cp = &g_Cpk[b][side][0][0][0];

    const int g = lane >> 2, t = lane & 3;
    const int n_r0 = nh * 128 + 16 * w + g;
    const int n_r1 = n_r0 + 8;
    const uint32_t c_off = (uint32_t)((lane & 7) + ((lane >> 4) << 3)) * (ASTR * 4)
                         + (((lane >> 3) & 1) << 4);

    // C fill decomposition: idx = tid + i*256 (i<2) -> var, m, q
    const int f_var = tid >> 8;               // always 0 for tid<256; use idx
    float accS[2][4][4], accF[2][4][4];
    #pragma unroll
    for (int mh = 0; mh < 2; mh++)
        #pragma unroll
        for (int gg = 0; gg < 4; gg++)
            #pragma unroll
            for (int r = 0; r < 4; r++) { accS[mh][gg][r] = 0.f; accF[mh][gg][r] = 0.f; }

    // ---- prefetch chunk 0 into stage 0
    #pragma unroll
    for (int i = 0; i < 2; i++) {
        int idx = tid + i * 256;
        int var = idx >> 8, rem = idx & 255;
        int m = rem >> 2, q = rem & 3;
        const uint32_t* src = Cp + (size_t)var * 256 * 128
                            + (size_t)(mq * 64 + m) * 128 + q * 4;
        cp16(smem_u32(&Cbuf[0][var][m * ASTR + q * 4]), src);
    }
    CP_COMMIT();

    for (int hc = 0; hc < 8; hc++) {
        const int buf = hc & 1;
        if (hc < 7) {
            const int nbuf = buf ^ 1;
            #pragma unroll
            for (int i = 0; i < 2; i++) {
                int idx = tid + i * 256;
                int var = idx >> 8, rem = idx & 255;
                int m = rem >> 2, q = rem & 3;
                const uint32_t* src = Cp + (size_t)var * 256 * 128
                                    + (size_t)(mq * 64 + m) * 128 + (hc + 1) * 16 + q * 4;
                cp16(smem_u32(&Cbuf[nbuf][var][m * ASTR + q * 4]), src);
            }
            CP_COMMIT();
            CP_WAIT(1);
        } else {
            CP_WAIT(0);
        }
        __syncthreads();   // chunk hc visible; prev buffer's readers done

        const uint32_t cHb = smem_u32(&Cbuf[buf][0][0]);
        const uint32_t cLb = smem_u32(&Cbuf[buf][1][0]);
        const int h0 = hc * 32;

        #pragma unroll
        for (int ks = 0; ks < 2; ks++) {
            const int h0k = h0 + ks * 16;
            float2 v00 = *(const float2*)(At + n_r0 * H_ + h0k + 2 * t);
            float2 v10 = *(const float2*)(At + n_r1 * H_ + h0k + 2 * t);
            float2 v01 = *(const float2*)(At + n_r0 * H_ + h0k + 2 * t + 8);
            float2 v11 = *(const float2*)(At + n_r1 * H_ + h0k + 2 * t + 8);
            float2 wa0 = *(const float2*)(watt_s + h0k + 2 * t);
            float2 wa1 = *(const float2*)(watt_s + h0k + 2 * t + 8);
            float2 wf0 = *(const float2*)(wfc_s  + h0k + 2 * t);
            float2 wf1 = *(const float2*)(wfc_s  + h0k + 2 * t + 8);

            uint32_t aSh[4], aSl[4], aFh[4], aFl[4];
            split2(wa0.x * v00.x, wa0.y * v00.y, aSh[0], aSl[0]);
            split2(wa0.x * v10.x, wa0.y * v10.y, aSh[1], aSl[1]);
            split2(wa1.x * v01.x, wa1.y * v01.y, aSh[2], aSl[2]);
            split2(wa1.x * v11.x, wa1.y * v11.y, aSh[3], aSl[3]);
            split2(wf0.x * v00.x, wf0.y * v00.y, aFh[0], aFl[0]);
            split2(wf0.x * v10.x, wf0.y * v10.y, aFh[1], aFl[1]);
            split2(wf1.x * v01.x, wf1.y * v01.y, aFh[2], aFl[2]);
            split2(wf1.x * v11.x, wf1.y * v11.y, aFh[3], aFl[3]);

            const uint32_t hkb = (uint32_t)(ks * 32);
            #pragma unroll
            for (int mh = 0; mh < 2; mh++) {
                const uint32_t mrow = (uint32_t)(mh * 32) * (ASTR * 4);
                uint32_t c[8];
                ldsm4(c + 0, cHb + mrow + c_off + hkb);
                ldsm4(c + 4, cHb + mrow + 16 * ASTR * 4 + c_off + hkb);
                #pragma unroll
                for (int gg = 0; gg < 4; gg++) {
                    mma_bf16(accS[mh][gg], aSh, c[2*gg], c[2*gg+1]);
                    mma_bf16(accS[mh][gg], aSl, c[2*gg], c[2*gg+1]);
                    mma_bf16(accF[mh][gg], aFh, c[2*gg], c[2*gg+1]);
                    mma_bf16(accF[mh][gg], aFl, c[2*gg], c[2*gg+1]);
                }
                ldsm4(c + 0, cLb + mrow + c_off + hkb);
                ldsm4(c + 4, cLb + mrow + 16 * ASTR * 4 + c_off + hkb);
                #pragma unroll
                for (int gg = 0; gg < 4; gg++) {
                    mma_bf16(accS[mh][gg], aSh, c[2*gg], c[2*gg+1]);
                    mma_bf16(accF[mh][gg], aFh, c[2*gg], c[2*gg+1]);
                }
            }
        }
        __syncthreads();   // readers of buffer `buf` done before refill next iter
    }

    // ---- epilogue: hybrid exp (even -> MUFU EX2, odd -> FMA-pipe poly)
    float num = 0.f, den = 0.f;
    #pragma unroll
    for (int mh = 0; mh < 2; mh++)
        #pragma unroll
        for (int gg = 0; gg < 4; gg++)
            #pragma unroll
            for (int r = 0; r < 4; r++) {
                float S = accS[mh][gg][r];
                float e = (r & 1) ? exp_poly(S) : __expf(S);
                den += e;
                num = fmaf(e, accF[mh][gg][r], num);
            }

    #pragma unroll
    for (int o = 16; o; o >>= 1) {
        num += __shfl_down_sync(0xffffffffu, num, o);
        den += __shfl_down_sync(0xffffffffu, den, o);
    }
    if (lane == 0) { rn[w] = num; rd[w] = den; }
    __syncthreads();
    if (tid == 0) {
        float sn = 0.f, sd = 0.f;
        #pragma unroll
        for (int q = 0; q < 8; q++) { sn += rn[q]; sd += rd[q]; }
        g_pnum[side][b][k][nh * 4 + mq] = sn;
        g_pden[side][b][k][nh * 4 + mq] = sd;
    }
}

// ---------------------------------------------------------------------------
// Finalize: loss = mean_b relu(score_n - score_p + margin). 256 threads.
// ---------------------------------------------------------------------------
__global__ void finalize_kernel(float* __restrict__ out) {
    __shared__ float sc[8][32];
    const int lane = threadIdx.x & 31;   // = b
    const int w    = threadIdx.x >> 5;
    float s = 0.f;
    #pragma unroll
    for (int pi = 0; pi < 2; pi++) {
        int p = w * 2 + pi;
        int side = p >> 3, k = p & 7;
        float n = 0.f, d = 0.f;
        #pragma unroll
        for (int q = 0; q < 8; q++) {
            n += g_pnum[side][lane][k][q];
            d += g_pden[side][lane][k][q];
        }
        float v = n / d;
        s += side ? v : -v;
    }
    sc[w][lane] = s;
    __syncthreads();
    if (w == 0) {
        float tot = 0.f;
        #pragma unroll
        for (int ww = 0; ww < 8; ww++) tot += sc[ww][lane];
        float v = fmaxf(tot + 0.2f, 0.f);
        #pragma unroll
        for (int o = 16; o; o >>= 1) v += __shfl_down_sync(0xffffffffu, v, o);
        if (lane == 0) out[0] = v * (1.0f / B_);
    }
}

// ---------------------------------------------------------------------------
extern "C" void kernel_launch(void* const* d_in, const int* in_sizes, int n_in,
                              void* d_out, int out_size) {
    const float* he_anchor = (const float*)d_in[0];
    const float* he_pos    = (const float*)d_in[1];
    const float* he_neg    = (const float*)d_in[2];
    const float* W_a2h     = (const float*)d_in[3];
    const float* b_a2h     = (const float*)d_in[4];
    const float* W_c2h     = (const float*)d_in[5];
    const float* b_c2h     = (const float*)d_in[6];
    const float* W_att     = (const float*)d_in[7];
    // d_in[8] = b_att : cancels in softmax
    const float* W_fc      = (const float*)d_in[9];
    // d_in[10] = b_fc : cancels in score difference

    wprep_kernel<<<2 * KSTEPS, 256>>>(W_a2h, W_c2h);

    projmma_kernel<<<dim3(4, 1, 96), 256>>>(he_anchor, he_pos, he_neg,
                                            b_a2h, b_c2h);

    score_kernel<<<dim3(64, B_, 2), 256>>>(W_att, W_fc);

    finalize_kernel<<<1, 256>>>((float*)d_out);
}

// round 13
// speedup vs baseline: 1.1143x; 1.0050x over previous
#include <cuda_runtime.h>
#include <cuda_bf16.h>
#include <cstdint>

// HGAN triplet loss. Projections and score bilinear forms on HMMA
// (mma.sync m16n8k16 bf16, fp32 acc, 3-pass hi/lo split).
// Score CTA = 128n x 64m (R10 proven config, 2 CTAs/SM) with cp.async
// double-buffered C staging.

#define B_ 32
#define N_ 256
#define E_ 300
#define H_ 256
#define K_ 8
#define KSTEPS 19     // ceil(300/16)

// ---------------------------------------------------------------------------
// Device scratch (allocation-free per harness rules)
// ---------------------------------------------------------------------------
__device__ float    g_projT[B_][N_][H_];             // anchor proj, [n][h]
__device__ uint32_t g_Cpk[B_][2][2][256][128];       // [b][side][hi/lo][m][h/2]
__device__ uint32_t g_Wpk[2][2][KSTEPS][256][8];     // [a2h/c2h][hi/lo][ks][h][k/2]
__device__ float    g_pnum[2][B_][K_][8];
__device__ float    g_pden[2][B_][K_][8];

// ---------------------------------------------------------------------------
// Helpers
// ---------------------------------------------------------------------------
__device__ __forceinline__ uint32_t smem_u32(const void* p) {
    uint32_t a;
    asm("{ .reg .u64 t; cvta.to.shared.u64 t, %1; cvt.u32.u64 %0, t; }" : "=r"(a) : "l"(p));
    return a;
}
__device__ __forceinline__ uint32_t cvt2(float v0, float v1) {
    uint32_t r;
    asm("cvt.rn.bf16x2.f32 %0, %1, %2;" : "=r"(r) : "f"(v1), "f"(v0));
    return r;
}
__device__ __forceinline__ void split2(float v0, float v1, uint32_t& uhi, uint32_t& ulo) {
    uhi = cvt2(v0, v1);
    float f0 = __uint_as_float(uhi << 16);
    float f1 = __uint_as_float(uhi & 0xffff0000u);
    ulo = cvt2(v0 - f0, v1 - f1);
}
__device__ __forceinline__ void ldsm4(uint32_t* r, uint32_t addr) {
    asm volatile("ldmatrix.sync.aligned.m8n8.x4.shared.b16 {%0,%1,%2,%3}, [%4];"
        : "=r"(r[0]), "=r"(r[1]), "=r"(r[2]), "=r"(r[3]) : "r"(addr));
}
__device__ __forceinline__ void mma_bf16(float* d, const uint32_t* a,
                                         uint32_t b0, uint32_t b1) {
    asm volatile("mma.sync.aligned.m16n8k16.row.col.f32.bf16.bf16.f32 "
        "{%0,%1,%2,%3}, {%4,%5,%6,%7}, {%8,%9}, {%0,%1,%2,%3};"
        : "+f"(d[0]), "+f"(d[1]), "+f"(d[2]), "+f"(d[3])
        : "r"(a[0]), "r"(a[1]), "r"(a[2]), "r"(a[3]), "r"(b0), "r"(b1));
}
__device__ __forceinline__ void cp16(uint32_t dst, const void* src) {
    asm volatile("cp.async.cg.shared.global [%0], [%1], 16;" :: "r"(dst), "l"(src));
}
#define CP_COMMIT() asm volatile("cp.async.commit_group;" ::: "memory")
#define CP_WAIT(n)  asm volatile("cp.async.wait_group %0;" :: "n"(n) : "memory")

// exp via 2^(x*log2e), deg-5 minimax poly (rel err ~3e-8), FMA-pipe only.
__device__ __forceinline__ float exp_poly(float x) {
    float t = x * 1.4426950408889634f;
    float fi = rintf(t);
    float f = t - fi;
    float p = 0.00133335581f;
    p = fmaf(p, f, 0.00961804886f);
    p = fmaf(p, f, 0.0555041087f);
    p = fmaf(p, f, 0.240226507f);
    p = fmaf(p, f, 0.69314718056f);
    p = fmaf(p, f, 1.0f);
    float s = __int_as_float(((int)fi + 127) << 23);
    return p * s;
}

// ---------------------------------------------------------------------------
// W prep (unchanged)
// ---------------------------------------------------------------------------
__global__ __launch_bounds__(256)
void wprep_kernel(const float* __restrict__ Wa, const float* __restrict__ Wc) {
    const int mode = blockIdx.x & 1, ks = blockIdx.x >> 1;
    const int h = threadIdx.x;
    const float* W = mode ? Wc : Wa;
    const int e0 = ks * 16;
    float v[16];
    #pragma unroll
    for (int j = 0; j < 16; j++)
        v[j] = (e0 + j < E_) ? W[h * E_ + e0 + j] : 0.f;
    #pragma unroll
    for (int i = 0; i < 8; i++) {
        uint32_t hi, lo;
        split2(v[2 * i], v[2 * i + 1], hi, lo);
        g_Wpk[mode][0][ks][h][i] = hi;
        g_Wpk[mode][1][ks][h][i] = lo;
    }
}

// ---------------------------------------------------------------------------
// Projection on HMMA (unchanged from R9/R10)
// ---------------------------------------------------------------------------
#define PSTR 12

__global__ __launch_bounds__(256, 2)
void projmma_kernel(const float* __restrict__ Xa, const float* __restrict__ Xp,
                    const float* __restrict__ Xn,
                    const float* __restrict__ ba, const float* __restrict__ bc) {
    __shared__ uint32_t XH[64 * PSTR], XL[64 * PSTR];
    __shared__ uint32_t WH[256 * PSTR], WL[256 * PSTR];
    __shared__ float bias_s[256];

    const int tid = threadIdx.x, lane = tid & 31, w = tid >> 5;
    const int nq = blockIdx.x;
    const int mb = blockIdx.z;
    const int mode = mb >> 5, b = mb & 31;

    const float* X    = (mode == 0) ? Xa : (mode == 1 ? Xp : Xn);
    const float* bias = (mode == 0) ? ba : bc;
    const int    wsel = (mode == 0) ? 0 : 1;

    bias_s[tid] = bias[tid];

    const float* Xbase = X + ((size_t)b * N_ + nq * 64) * E_;
    const int warp_n = w & 3, warp_h = w >> 2;

    const uint32_t xhb = smem_u32(XH), xlb = smem_u32(XL);
    const uint32_t whb = smem_u32(WH), wlb = smem_u32(WL);

    const uint32_t a_off = (uint32_t)(warp_n * 16 + (lane & 15)) * 48 + ((lane >> 4) << 4);
    const uint32_t c_off = (uint32_t)((lane & 7) + ((lane >> 4) << 3)) * 48
                         + (((lane >> 3) & 1) << 4);

    const int fx_n = tid >> 2, fx_q = tid & 3;

    float acc[16][4];
    #pragma unroll
    for (int i = 0; i < 16; i++)
        #pragma unroll
        for (int j = 0; j < 4; j++) acc[i][j] = 0.f;

    for (int ks = 0; ks < KSTEPS; ks++) {
        const int e0 = ks * 16;
        __syncthreads();

        {
            float4 v = make_float4(0.f, 0.f, 0.f, 0.f);
            if (e0 + fx_q * 4 < E_)
                v = *(const float4*)(Xbase + fx_n * E_ + e0 + fx_q * 4);
            uint32_t h0, l0, h1, l1;
            split2(v.x, v.y, h0, l0);
            split2(v.z, v.w, h1, l1);
            const int o = fx_n * PSTR + fx_q * 2;
            XH[o] = h0; XH[o + 1] = h1;
            XL[o] = l0; XL[o + 1] = l1;
        }
        #pragma unroll
        for (int i = 0; i < 4; i++) {
            int idx = tid + i * 256;
            int var = idx >> 9, rem = idx & 511;
            int h = rem >> 1, half = rem & 1;
            uint4 v = *(const uint4*)&g_Wpk[wsel][var][ks][h][half * 4];
            uint32_t* dst = (var ? WL : WH) + h * PSTR + half * 4;
            *(uint4*)dst = v;
        }
        __syncthreads();

        uint32_t aH[4], aL[4];
        ldsm4(aH, xhb + a_off);
        ldsm4(aL, xlb + a_off);
        #pragma unroll
        for (int qh = 0; qh < 4; qh++) {
            const uint32_t hb = (uint32_t)(warp_h * 128 + qh * 32) * 48;
            uint32_t bh[8], bl[8];
            ldsm4(bh + 0, whb + hb + c_off);
            ldsm4(bh + 4, whb + hb + 16 * 48 + c_off);
            ldsm4(bl + 0, wlb + hb + c_off);
            ldsm4(bl + 4, wlb + hb + 16 * 48 + c_off);
            #pragma unroll
            for (int t2 = 0; t2 < 4; t2++) {
                const int ht = qh * 4 + t2;
                mma_bf16(acc[ht], aH, bh[2 * t2], bh[2 * t2 + 1]);
                mma_bf16(acc[ht], aL, bh[2 * t2], bh[2 * t2 + 1]);
                mma_bf16(acc[ht], aH, bl[2 * t2], bl[2 * t2 + 1]);
            }
        }
    }

    const int g = lane >> 2, q = lane & 3;
    const int n0 = nq * 64 + warp_n * 16 + g;
    #pragma unroll
    for (int ht = 0; ht < 16; ht++) {
        const int h = warp_h * 128 + ht * 8 + 2 * q;
        const float b0 = bias_s[h], b1 = bias_s[h + 1];
        const float x0 = acc[ht][0] + b0, x1 = acc[ht][1] + b1;
        const float x2 = acc[ht][2] + b0, x3 = acc[ht][3] + b1;
        if (mode == 0) {
            *(float2*)&g_projT[b][n0][h]     = make_float2(x0, x1);
            *(float2*)&g_projT[b][n0 + 8][h] = make_float2(x2, x3);
        } else {
            const int side = mode - 1;
            uint32_t hi, lo;
            split2(x0, x1, hi, lo);
            g_Cpk[b][side][0][n0][h >> 1] = hi;
            g_Cpk[b][side][1][n0][h >> 1] = lo;
            split2(x2, x3, hi, lo);
            g_Cpk[b][side][0][n0 + 8][h >> 1] = hi;
            g_Cpk[b][side][1][n0 + 8][h >> 1] = lo;
        }
    }
}

// ---------------------------------------------------------------------------
// Score: CTA = 128n x 64m slice of one (k, b, side). bx = k + 8*mq + 32*nh.
// (R10 proven tiling, 2 CTAs/SM.) C staged via cp.async, double-buffered.
// A fragments built in registers (LDG fp32 -> scale -> hi/lo split).
// ---------------------------------------------------------------------------
#define ASTR 20                       // u32 row stride (80 B, conflict-free)
#define CB_U32 (64 * ASTR)            // 1280 u32 per hi/lo buffer

__global__ __launch_bounds__(256, 2)
void score_kernel(const float* __restrict__ W_att, const float* __restrict__ W_fc) {
    __shared__ uint32_t Cbuf[2][2][CB_U32];   // [stage][hi/lo][...]
    __shared__ float watt_s[H_], wfc_s[H_];
    __shared__ float rn[8], rd[8];

    const int tid  = threadIdx.x;
    const int lane = tid & 31, w = tid >> 5;
    const int k  = blockIdx.x & 7;
    const int mq = (blockIdx.x >> 3) & 3;
    const int nh = blockIdx.x >> 5;
    const int b = blockIdx.y, side = blockIdx.z;

    watt_s[tid] = W_att[k * H_ + tid];
    wfc_s [tid] = W_fc [k * H_ + tid];

    const float*    At = &g_projT[b][0][0];
    const uint32_t* Cp = &g_Cpk[b][side][0][0][0];

    const int g = lane >> 2, t = lane & 3;
    const int n_r0 = nh * 128 + 16 * w + g;
    const int n_r1 = n_r0 + 8;
    const uint32_t c_off = (uint32_t)((lane & 7) + ((lane >> 4) << 3)) * (ASTR * 4)
                         + (((lane >> 3) & 1) << 4);

    // C fill decomposition: idx = tid + i*256 (i<2) -> var, m, q
    const int f_var = tid >> 8;               // always 0 for tid<256; use idx
    float accS[2][4][4], accF[2][4][4];
    #pragma unroll
    for (int mh = 0; mh < 2; mh++)
        #pragma unroll
        for (int gg = 0; gg < 4; gg++)
            #pragma unroll
            for (int r = 0; r < 4; r++) { accS[mh][gg][r] = 0.f; accF[mh][gg][r] = 0.f; }

    // ---- prefetch chunk 0 into stage 0
    #pragma unroll
    for (int i = 0; i < 2; i++) {
        int idx = tid + i * 256;
        int var = idx >> 8, rem = idx & 255;
        int m = rem >> 2, q = rem & 3;
        const uint32_t* src = Cp + (size_t)var * 256 * 128
                            + (size_t)(mq * 64 + m) * 128 + q * 4;
        cp16(smem_u32(&Cbuf[0][var][m * ASTR + q * 4]), src);
    }
    CP_COMMIT();

    for (int hc = 0; hc < 8; hc++) {
        const int buf = hc & 1;
        if (hc < 7) {
            const int nbuf = buf ^ 1;
            #pragma unroll
            for (int i = 0; i < 2; i++) {
                int idx = tid + i * 256;
                int var = idx >> 8, rem = idx & 255;
                int m = rem >> 2, q = rem & 3;
                const uint32_t* src = Cp + (size_t)var * 256 * 128
                                    + (size_t)(mq * 64 + m) * 128 + (hc + 1) * 16 + q * 4;
                cp16(smem_u32(&Cbuf[nbuf][var][m * ASTR + q * 4]), src);
            }
            CP_COMMIT();
            CP_WAIT(1);
        } else {
            CP_WAIT(0);
        }
        __syncthreads();   // chunk hc visible; prev buffer's readers done

        const uint32_t cHb = smem_u32(&Cbuf[buf][0][0]);
        const uint32_t cLb = smem_u32(&Cbuf[buf][1][0]);
        const int h0 = hc * 32;

        #pragma unroll
        for (int ks = 0; ks < 2; ks++) {
            const int h0k = h0 + ks * 16;
            float2 v00 = *(const float2*)(At + n_r0 * H_ + h0k + 2 * t);
            float2 v10 = *(const float2*)(At + n_r1 * H_ + h0k + 2 * t);
            float2 v01 = *(const float2*)(At + n_r0 * H_ + h0k + 2 * t + 8);
            float2 v11 = *(const float2*)(At + n_r1 * H_ + h0k + 2 * t + 8);
            float2 wa0 = *(const float2*)(watt_s + h0k + 2 * t);
            float2 wa1 = *(const float2*)(watt_s + h0k + 2 * t + 8);
            float2 wf0 = *(const float2*)(wfc_s  + h0k + 2 * t);
            float2 wf1 = *(const float2*)(wfc_s  + h0k + 2 * t + 8);

            uint32_t aSh[4], aSl[4], aFh[4], aFl[4];
            split2(wa0.x * v00.x, wa0.y * v00.y, aSh[0], aSl[0]);
            split2(wa0.x * v10.x, wa0.y * v10.y, aSh[1], aSl[1]);
            split2(wa1.x * v01.x, wa1.y * v01.y, aSh[2], aSl[2]);
            split2(wa1.x * v11.x, wa1.y * v11.y, aSh[3], aSl[3]);
            split2(wf0.x * v00.x, wf0.y * v00.y, aFh[0], aFl[0]);
            split2(wf0.x * v10.x, wf0.y * v10.y, aFh[1], aFl[1]);
            split2(wf1.x * v01.x, wf1.y * v01.y, aFh[2], aFl[2]);
            split2(wf1.x * v11.x, wf1.y * v11.y, aFh[3], aFl[3]);

            const uint32_t hkb = (uint32_t)(ks * 32);
            #pragma unroll
            for (int mh = 0; mh < 2; mh++) {
                const uint32_t mrow = (uint32_t)(mh * 32) * (ASTR * 4);
                uint32_t c[8];
                ldsm4(c + 0, cHb + mrow + c_off + hkb);
                ldsm4(c + 4, cHb + mrow + 16 * ASTR * 4 + c_off + hkb);
                #pragma unroll
                for (int gg = 0; gg < 4; gg++) {
                    mma_bf16(accS[mh][gg], aSh, c[2*gg], c[2*gg+1]);
                    mma_bf16(accS[mh][gg], aSl, c[2*gg], c[2*gg+1]);
                    mma_bf16(accF[mh][gg], aFh, c[2*gg], c[2*gg+1]);
                    mma_bf16(accF[mh][gg], aFl, c[2*gg], c[2*gg+1]);
                }
                ldsm4(c + 0, cLb + mrow + c_off + hkb);
                ldsm4(c + 4, cLb + mrow + 16 * ASTR * 4 + c_off + hkb);
                #pragma unroll
                for (int gg = 0; gg < 4; gg++) {
                    mma_bf16(accS[mh][gg], aSh, c[2*gg], c[2*gg+1]);
                    mma_bf16(accF[mh][gg], aFh, c[2*gg], c[2*gg+1]);
                }
            }
        }
        __syncthreads();   // readers of buffer `buf` done before refill next iter
    }

    // ---- epilogue: hybrid exp (even -> MUFU EX2, odd -> FMA-pipe poly)
    float num = 0.f, den = 0.f;
    #pragma unroll
    for (int mh = 0; mh < 2; mh++)
        #pragma unroll
        for (int gg = 0; gg < 4; gg++)
            #pragma unroll
            for (int r = 0; r < 4; r++) {
                float S = accS[mh][gg][r];
                float e = (r & 1) ? exp_poly(S) : __expf(S);
                den += e;
                num = fmaf(e, accF[mh][gg][r], num);
            }

    #pragma unroll
    for (int o = 16; o; o >>= 1) {
        num += __shfl_down_sync(0xffffffffu, num, o);
        den += __shfl_down_sync(0xffffffffu, den, o);
    }
    if (lane == 0) { rn[w] = num; rd[w] = den; }
    __syncthreads();
    if (tid == 0) {
        float sn = 0.f, sd = 0.f;
        #pragma unroll
        for (int q = 0; q < 8; q++) { sn += rn[q]; sd += rd[q]; }
        g_pnum[side][b][k][nh * 4 + mq] = sn;
        g_pden[side][b][k][nh * 4 + mq] = sd;
    }
}

// ---------------------------------------------------------------------------
// Finalize: loss = mean_b relu(score_n - score_p + margin). 256 threads.
// ---------------------------------------------------------------------------
__global__ void finalize_kernel(float* __restrict__ out) {
    __shared__ float sc[8][32];
    const int lane = threadIdx.x & 31;   // = b
    const int w    = threadIdx.x >> 5;
    float s = 0.f;
    #pragma unroll
    for (int pi = 0; pi < 2; pi++) {
        int p = w * 2 + pi;
        int side = p >> 3, k = p & 7;
        float n = 0.f, d = 0.f;
        #pragma unroll
        for (int q = 0; q < 8; q++) {
            n += g_pnum[side][lane][k][q];
            d += g_pden[side][lane][k][q];
        }
        float v = n / d;
        s += side ? v : -v;
    }
    sc[w][lane] = s;
    __syncthreads();
    if (w == 0) {
        float tot = 0.f;
        #pragma unroll
        for (int ww = 0; ww < 8; ww++) tot += sc[ww][lane];
        float v = fmaxf(tot + 0.2f, 0.f);
        #pragma unroll
        for (int o = 16; o; o >>= 1) v += __shfl_down_sync(0xffffffffu, v, o);
        if (lane == 0) out[0] = v * (1.0f / B_);
    }
}

// ---------------------------------------------------------------------------
extern "C" void kernel_launch(void* const* d_in, const int* in_sizes, int n_in,
                              void* d_out, int out_size) {
    const float* he_anchor = (const float*)d_in[0];
    const float* he_pos    = (const float*)d_in[1];
    const float* he_neg    = (const float*)d_in[2];
    const float* W_a2h     = (const float*)d_in[3];
    const float* b_a2h     = (const float*)d_in[4];
    const float* W_c2h     = (const float*)d_in[5];
    const float* b_c2h     = (const float*)d_in[6];
    const float* W_att     = (const float*)d_in[7];
    // d_in[8] = b_att : cancels in softmax
    const float* W_fc      = (const float*)d_in[9];
    // d_in[10] = b_fc : cancels in score difference

    wprep_kernel<<<2 * KSTEPS, 256>>>(W_a2h, W_c2h);

    projmma_kernel<<<dim3(4, 1, 96), 256>>>(he_anchor, he_pos, he_neg,
                                            b_a2h, b_c2h);

    score_kernel<<<dim3(64, B_, 2), 256>>>(W_att, W_fc);

    finalize_kernel<<<1, 256>>>((float*)d_out);
}

// round 14
// speedup vs baseline: 1.1841x; 1.0627x over previous
#include <cuda_runtime.h>
#include <cuda_bf16.h>
#include <cstdint>

// HGAN triplet loss. Projections and score bilinear forms on HMMA
// (mma.sync m16n8k16 bf16, fp32 acc, 3-pass hi/lo split).
//   S = sum_h Aa[h,n] * (watt[h]*Ac[h,m]),  F = sum_h Aa[h,n] * (wfc[h]*Ac[h,m])
// Anchor A is k-independent: projmma emits ready mma fragments (hi/lo pack).
// The per-k scaling+split happens on the C side in smem, once per h-chunk.

#define B_ 32
#define N_ 256
#define E_ 300
#define H_ 256
#define K_ 8
#define KSTEPS 19     // ceil(300/16)

// ---------------------------------------------------------------------------
// Device scratch (allocation-free per harness rules)
// ---------------------------------------------------------------------------
__device__ uint32_t g_Apk[B_][16][16][2][32][4];     // [b][ntile][ks][hi/lo][lane][frag], 8 MB
__device__ float    g_projS[2][B_][256][H_];         // pos/neg proj fp32, [m][h], 16 MB
__device__ float    g_pnum[2][B_][K_][8];
__device__ float    g_pden[2][B_][K_][8];
__device__ uint32_t g_Wpk[2][2][KSTEPS][256][8];     // [a2h/c2h][hi/lo][ks][h][k/2]

// ---------------------------------------------------------------------------
// Helpers
// ---------------------------------------------------------------------------
__device__ __forceinline__ uint32_t smem_u32(const void* p) {
    uint32_t a;
    asm("{ .reg .u64 t; cvta.to.shared.u64 t, %1; cvt.u32.u64 %0, t; }" : "=r"(a) : "l"(p));
    return a;
}
__device__ __forceinline__ uint32_t cvt2(float v0, float v1) {
    uint32_t r;
    asm("cvt.rn.bf16x2.f32 %0, %1, %2;" : "=r"(r) : "f"(v1), "f"(v0));
    return r;
}
__device__ __forceinline__ void split2(float v0, float v1, uint32_t& uhi, uint32_t& ulo) {
    uhi = cvt2(v0, v1);
    float f0 = __uint_as_float(uhi << 16);
    float f1 = __uint_as_float(uhi & 0xffff0000u);
    ulo = cvt2(v0 - f0, v1 - f1);
}
__device__ __forceinline__ void ldsm4(uint32_t* r, uint32_t addr) {
    asm volatile("ldmatrix.sync.aligned.m8n8.x4.shared.b16 {%0,%1,%2,%3}, [%4];"
        : "=r"(r[0]), "=r"(r[1]), "=r"(r[2]), "=r"(r[3]) : "r"(addr));
}
__device__ __forceinline__ void mma_bf16(float* d, const uint32_t* a,
                                         uint32_t b0, uint32_t b1) {
    asm volatile("mma.sync.aligned.m16n8k16.row.col.f32.bf16.bf16.f32 "
        "{%0,%1,%2,%3}, {%4,%5,%6,%7}, {%8,%9}, {%0,%1,%2,%3};"
        : "+f"(d[0]), "+f"(d[1]), "+f"(d[2]), "+f"(d[3])
        : "r"(a[0]), "r"(a[1]), "r"(a[2]), "r"(a[3]), "r"(b0), "r"(b1));
}
// exp via 2^(x*log2e), deg-5 minimax poly (rel err ~3e-8), FMA-pipe only.
__device__ __forceinline__ float exp_poly(float x) {
    float t = x * 1.4426950408889634f;
    float fi = rintf(t);
    float f = t - fi;
    float p = 0.00133335581f;
    p = fmaf(p, f, 0.00961804886f);
    p = fmaf(p, f, 0.0555041087f);
    p = fmaf(p, f, 0.240226507f);
    p = fmaf(p, f, 0.69314718056f);
    p = fmaf(p, f, 1.0f);
    float s = __int_as_float(((int)fi + 127) << 23);
    return p * s;
}

// ---------------------------------------------------------------------------
// W prep (unchanged)
// ---------------------------------------------------------------------------
__global__ __launch_bounds__(256)
void wprep_kernel(const float* __restrict__ Wa, const float* __restrict__ Wc) {
    const int mode = blockIdx.x & 1, ks = blockIdx.x >> 1;
    const int h = threadIdx.x;
    const float* W = mode ? Wc : Wa;
    const int e0 = ks * 16;
    float v[16];
    #pragma unroll
    for (int j = 0; j < 16; j++)
        v[j] = (e0 + j < E_) ? W[h * E_ + e0 + j] : 0.f;
    #pragma unroll
    for (int i = 0; i < 8; i++) {
        uint32_t hi, lo;
        split2(v[2 * i], v[2 * i + 1], hi, lo);
        g_Wpk[mode][0][ks][h][i] = hi;
        g_Wpk[mode][1][ks][h][i] = lo;
    }
}

// ---------------------------------------------------------------------------
// Projection on HMMA (mainloop unchanged from R9/R10).
// Epilogue: mode 0 (anchor) -> ready hi/lo A-fragments (g_Apk);
//           mode 1/2 (pos/neg) -> fp32 g_projS.
// ---------------------------------------------------------------------------
#define PSTR 12

__global__ __launch_bounds__(256, 2)
void projmma_kernel(const float* __restrict__ Xa, const float* __restrict__ Xp,
                    const float* __restrict__ Xn,
                    const float* __restrict__ ba, const float* __restrict__ bc) {
    __shared__ uint32_t XH[64 * PSTR], XL[64 * PSTR];
    __shared__ uint32_t WH[256 * PSTR], WL[256 * PSTR];
    __shared__ float bias_s[256];

    const int tid = threadIdx.x, lane = tid & 31, w = tid >> 5;
    const int nq = blockIdx.x;
    const int mb = blockIdx.z;
    const int mode = mb >> 5, b = mb & 31;

    const float* X    = (mode == 0) ? Xa : (mode == 1 ? Xp : Xn);
    const float* bias = (mode == 0) ? ba : bc;
    const int    wsel = (mode == 0) ? 0 : 1;

    bias_s[tid] = bias[tid];

    const float* Xbase = X + ((size_t)b * N_ + nq * 64) * E_;
    const int warp_n = w & 3, warp_h = w >> 2;

    const uint32_t xhb = smem_u32(XH), xlb = smem_u32(XL);
    const uint32_t whb = smem_u32(WH), wlb = smem_u32(WL);

    const uint32_t a_off = (uint32_t)(warp_n * 16 + (lane & 15)) * 48 + ((lane >> 4) << 4);
    const uint32_t c_off = (uint32_t)((lane & 7) + ((lane >> 4) << 3)) * 48
                         + (((lane >> 3) & 1) << 4);

    const int fx_n = tid >> 2, fx_q = tid & 3;

    float acc[16][4];
    #pragma unroll
    for (int i = 0; i < 16; i++)
        #pragma unroll
        for (int j = 0; j < 4; j++) acc[i][j] = 0.f;

    for (int ks = 0; ks < KSTEPS; ks++) {
        const int e0 = ks * 16;
        __syncthreads();

        {
            float4 v = make_float4(0.f, 0.f, 0.f, 0.f);
            if (e0 + fx_q * 4 < E_)
                v = *(const float4*)(Xbase + fx_n * E_ + e0 + fx_q * 4);
            uint32_t h0, l0, h1, l1;
            split2(v.x, v.y, h0, l0);
            split2(v.z, v.w, h1, l1);
            const int o = fx_n * PSTR + fx_q * 2;
            XH[o] = h0; XH[o + 1] = h1;
            XL[o] = l0; XL[o + 1] = l1;
        }
        #pragma unroll
        for (int i = 0; i < 4; i++) {
            int idx = tid + i * 256;
            int var = idx >> 9, rem = idx & 511;
            int h = rem >> 1, half = rem & 1;
            uint4 v = *(const uint4*)&g_Wpk[wsel][var][ks][h][half * 4];
            uint32_t* dst = (var ? WL : WH) + h * PSTR + half * 4;
            *(uint4*)dst = v;
        }
        __syncthreads();

        uint32_t aH[4], aL[4];
        ldsm4(aH, xhb + a_off);
        ldsm4(aL, xlb + a_off);
        #pragma unroll
        for (int qh = 0; qh < 4; qh++) {
            const uint32_t hb = (uint32_t)(warp_h * 128 + qh * 32) * 48;
            uint32_t bh[8], bl[8];
            ldsm4(bh + 0, whb + hb + c_off);
            ldsm4(bh + 4, whb + hb + 16 * 48 + c_off);
            ldsm4(bl + 0, wlb + hb + c_off);
            ldsm4(bl + 4, wlb + hb + 16 * 48 + c_off);
            #pragma unroll
            for (int t2 = 0; t2 < 4; t2++) {
                const int ht = qh * 4 + t2;
                mma_bf16(acc[ht], aH, bh[2 * t2], bh[2 * t2 + 1]);
                mma_bf16(acc[ht], aL, bh[2 * t2], bh[2 * t2 + 1]);
                mma_bf16(acc[ht], aH, bl[2 * t2], bl[2 * t2 + 1]);
            }
        }
    }

    const int g = lane >> 2, q = lane & 3;
    if (mode == 0) {
        // A-fragment pack: thread (g,q) holds, for each ht, cols (2q,2q+1)
        // [+8 for odd ht] of rows (n0, n0+8). ks = warp_h*8 + ht/2.
        const int nt = nq * 4 + warp_n;
        #pragma unroll
        for (int ht2 = 0; ht2 < 8; ht2++) {
            const int ks = warp_h * 8 + ht2;
            const int he = 2 * ht2, ho = he + 1;
            const int hbe = warp_h * 128 + he * 8 + 2 * q;
            const int hbo = hbe + 8;
            uint32_t fh[4], fl[4];
            split2(acc[he][0] + bias_s[hbe], acc[he][1] + bias_s[hbe + 1], fh[0], fl[0]);
            split2(acc[he][2] + bias_s[hbe], acc[he][3] + bias_s[hbe + 1], fh[1], fl[1]);
            split2(acc[ho][0] + bias_s[hbo], acc[ho][1] + bias_s[hbo + 1], fh[2], fl[2]);
            split2(acc[ho][2] + bias_s[hbo], acc[ho][3] + bias_s[hbo + 1], fh[3], fl[3]);
            *(uint4*)&g_Apk[b][nt][ks][0][lane][0] = *(uint4*)fh;
            *(uint4*)&g_Apk[b][nt][ks][1][lane][0] = *(uint4*)fl;
        }
    } else {
        const int side = mode - 1;
        const int n0 = nq * 64 + warp_n * 16 + g;
        #pragma unroll
        for (int ht = 0; ht < 16; ht++) {
            const int h = warp_h * 128 + ht * 8 + 2 * q;
            const float b0 = bias_s[h], b1 = bias_s[h + 1];
            *(float2*)&g_projS[side][b][n0][h]     = make_float2(acc[ht][0] + b0, acc[ht][1] + b1);
            *(float2*)&g_projS[side][b][n0 + 8][h] = make_float2(acc[ht][2] + b0, acc[ht][3] + b1);
        }
    }
}

// ---------------------------------------------------------------------------
// Score: CTA = 128n x 64m slice of one (k, b, side). bx = k + 8*mq + 32*nh.
// A: ready fragments from g_Apk (2x LDG.128 per ks, no ALU).
// C: 4 smem variants (S-hi, S-lo, F-hi, F-lo) built per h-chunk from fp32
//    g_projS scaled by watt/wfc, split.
// ---------------------------------------------------------------------------
#define ASTR 20   // u32 row stride (80 B, conflict-free)

__global__ __launch_bounds__(256, 2)
void score_kernel(const float* __restrict__ W_att, const float* __restrict__ W_fc) {
    __shared__ uint32_t CSh[64 * ASTR], CSl[64 * ASTR];
    __shared__ uint32_t CFh[64 * ASTR], CFl[64 * ASTR];
    __shared__ float watt_s[H_], wfc_s[H_];
    __shared__ float rn[8], rd[8];

    const int tid  = threadIdx.x;
    const int lane = tid & 31, w = tid >> 5;
    const int k  = blockIdx.x & 7;
    const int mq = (blockIdx.x >> 3) & 3;
    const int nh = blockIdx.x >> 5;
    const int b = blockIdx.y, side = blockIdx.z;

    watt_s[tid] = W_att[k * H_ + tid];
    wfc_s [tid] = W_fc [k * H_ + tid];

    const float* Cs = &g_projS[side][b][0][0];
    const uint32_t cSh = smem_u32(CSh), cSl = smem_u32(CSl);
    const uint32_t cFh = smem_u32(CFh), cFl = smem_u32(CFl);

    const int nt = nh * 8 + w;           // this warp's A n-tile
    const uint32_t c_off = (uint32_t)((lane & 7) + ((lane >> 4) << 3)) * (ASTR * 4)
                         + (((lane >> 3) & 1) << 4);

    // C-build decomposition: thread -> m = tid>>2, h-octet hq = tid&3
    const int cb_m = tid >> 2, cb_hq = tid & 3;
    const float* cb_src = Cs + (size_t)(mq * 64 + cb_m) * H_ + cb_hq * 8;
    const int cb_o = cb_m * ASTR + cb_hq * 4;

    float accS[2][4][4], accF[2][4][4];
    #pragma unroll
    for (int mh = 0; mh < 2; mh++)
        #pragma unroll
        for (int gg = 0; gg < 4; gg++)
            #pragma unroll
            for (int r = 0; r < 4; r++) { accS[mh][gg][r] = 0.f; accF[mh][gg][r] = 0.f; }

    for (int hc = 0; hc < 8; hc++) {
        const int h0 = hc * 32;
        __syncthreads();   // previous chunk's ldsm reads done

        // ---- C build: 64m x 32h, scale by watt/wfc, hi/lo split
        {
            const float* s = cb_src + h0;
            const int hh = h0 + cb_hq * 8;
            #pragma unroll
            for (int jp = 0; jp < 4; jp += 2) {
                float2 v0 = *(const float2*)(s + 2 * jp);
                float2 v1 = *(const float2*)(s + 2 * jp + 2);
                float2 wa0 = *(const float2*)(watt_s + hh + 2 * jp);
                float2 wa1 = *(const float2*)(watt_s + hh + 2 * jp + 2);
                float2 wf0 = *(const float2*)(wfc_s  + hh + 2 * jp);
                float2 wf1 = *(const float2*)(wfc_s  + hh + 2 * jp + 2);
                uint32_t h0a, l0a, h1a, l1a;
                split2(wa0.x * v0.x, wa0.y * v0.y, h0a, l0a);
                split2(wa1.x * v1.x, wa1.y * v1.y, h1a, l1a);
                *(uint2*)&CSh[cb_o + jp] = make_uint2(h0a, h1a);
                *(uint2*)&CSl[cb_o + jp] = make_uint2(l0a, l1a);
                split2(wf0.x * v0.x, wf0.y * v0.y, h0a, l0a);
                split2(wf1.x * v1.x, wf1.y * v1.y, h1a, l1a);
                *(uint2*)&CFh[cb_o + jp] = make_uint2(h0a, h1a);
                *(uint2*)&CFl[cb_o + jp] = make_uint2(l0a, l1a);
            }
        }
        __syncthreads();   // build visible

        #pragma unroll
        for (int ks = 0; ks < 2; ks++) {
            const int ksg = hc * 2 + ks;
            uint32_t aH[4], aL[4];
            *(uint4*)aH = *(const uint4*)&g_Apk[b][nt][ksg][0][lane][0];
            *(uint4*)aL = *(const uint4*)&g_Apk[b][nt][ksg][1][lane][0];

            const uint32_t hkb = (uint32_t)(ks * 32);
            #pragma unroll
            for (int mh = 0; mh < 2; mh++) {
                const uint32_t mrow = (uint32_t)(mh * 32) * (ASTR * 4);
                uint32_t c[8];
                // S hi
                ldsm4(c + 0, cSh + mrow + c_off + hkb);
                ldsm4(c + 4, cSh + mrow + 16 * ASTR * 4 + c_off + hkb);
                #pragma unroll
                for (int gg = 0; gg < 4; gg++) {
                    mma_bf16(accS[mh][gg], aH, c[2*gg], c[2*gg+1]);
                    mma_bf16(accS[mh][gg], aL, c[2*gg], c[2*gg+1]);
                }
                // S lo
                ldsm4(c + 0, cSl + mrow + c_off + hkb);
                ldsm4(c + 4, cSl + mrow + 16 * ASTR * 4 + c_off + hkb);
                #pragma unroll
                for (int gg = 0; gg < 4; gg++)
                    mma_bf16(accS[mh][gg], aH, c[2*gg], c[2*gg+1]);
                // F hi
                ldsm4(c + 0, cFh + mrow + c_off + hkb);
                ldsm4(c + 4, cFh + mrow + 16 * ASTR * 4 + c_off + hkb);
                #pragma unroll
                for (int gg = 0; gg < 4; gg++) {
                    mma_bf16(accF[mh][gg], aH, c[2*gg], c[2*gg+1]);
                    mma_bf16(accF[mh][gg], aL, c[2*gg], c[2*gg+1]);
                }
                // F lo
                ldsm4(c + 0, cFl + mrow + c_off + hkb);
                ldsm4(c + 4, cFl + mrow + 16 * ASTR * 4 + c_off + hkb);
                #pragma unroll
                for (int gg = 0; gg < 4; gg++)
                    mma_bf16(accF[mh][gg], aH, c[2*gg], c[2*gg+1]);
            }
        }
    }

    // ---- epilogue: hybrid exp (even -> MUFU EX2, odd -> FMA-pipe poly)
    float num = 0.f, den = 0.f;
    #pragma unroll
    for (int mh = 0; mh < 2; mh++)
        #pragma unroll
        for (int gg = 0; gg < 4; gg++)
            #pragma unroll
            for (int r = 0; r < 4; r++) {
                float S = accS[mh][gg][r];
                float e = (r & 1) ? exp_poly(S) : __expf(S);
                den += e;
                num = fmaf(e, accF[mh][gg][r], num);
            }

    #pragma unroll
    for (int o = 16; o; o >>= 1) {
        num += __shfl_down_sync(0xffffffffu, num, o);
        den += __shfl_down_sync(0xffffffffu, den, o);
    }
    if (lane == 0) { rn[w] = num; rd[w] = den; }
    __syncthreads();
    if (tid == 0) {
        float sn = 0.f, sd = 0.f;
        #pragma unroll
        for (int q = 0; q < 8; q++) { sn += rn[q]; sd += rd[q]; }
        g_pnum[side][b][k][nh * 4 + mq] = sn;
        g_pden[side][b][k][nh * 4 + mq] = sd;
    }
}

// ---------------------------------------------------------------------------
// Finalize: loss = mean_b relu(score_n - score_p + margin). 256 threads.
// ---------------------------------------------------------------------------
__global__ void finalize_kernel(float* __restrict__ out) {
    __shared__ float sc[8][32];
    const int lane = threadIdx.x & 31;   // = b
    const int w    = threadIdx.x >> 5;
    float s = 0.f;
    #pragma unroll
    for (int pi = 0; pi < 2; pi++) {
        int p = w * 2 + pi;
        int side = p >> 3, k = p & 7;
        float n = 0.f, d = 0.f;
        #pragma unroll
        for (int q = 0; q < 8; q++) {
            n += g_pnum[side][lane][k][q];
            d += g_pden[side][lane][k][q];
        }
        float v = n / d;
        s += side ? v : -v;
    }
    sc[w][lane] = s;
    __syncthreads();
    if (w == 0) {
        float tot = 0.f;
        #pragma unroll
        for (int ww = 0; ww < 8; ww++) tot += sc[ww][lane];
        float v = fmaxf(tot + 0.2f, 0.f);
        #pragma unroll
        for (int o = 16; o; o >>= 1) v += __shfl_down_sync(0xffffffffu, v, o);
        if (lane == 0) out[0] = v * (1.0f / B_);
    }
}

// ---------------------------------------------------------------------------
extern "C" void kernel_launch(void* const* d_in, const int* in_sizes, int n_in,
                              void* d_out, int out_size) {
    const float* he_anchor = (const float*)d_in[0];
    const float* he_pos    = (const float*)d_in[1];
    const float* he_neg    = (const float*)d_in[2];
    const float* W_a2h     = (const float*)d_in[3];
    const float* b_a2h     = (const float*)d_in[4];
    const float* W_c2h     = (const float*)d_in[5];
    const float* b_c2h     = (const float*)d_in[6];
    const float* W_att     = (const float*)d_in[7];
    // d_in[8] = b_att : cancels in softmax
    const float* W_fc      = (const float*)d_in[9];
    // d_in[10] = b_fc : cancels in score difference

    wprep_kernel<<<2 * KSTEPS, 256>>>(W_a2h, W_c2h);

    projmma_kernel<<<dim3(4, 1, 96), 256>>>(he_anchor, he_pos, he_neg,
                                            b_a2h, b_c2h);

    score_kernel<<<dim3(64, B_, 2), 256>>>(W_att, W_fc);

    finalize_kernel<<<1, 256>>>((float*)d_out);
}

// round 15
// speedup vs baseline: 1.2125x; 1.0239x over previous
#include <cuda_runtime.h>
#include <cuda_bf16.h>
#include <cstdint>

// HGAN triplet loss. Projections and score bilinear forms on HMMA
// (mma.sync m16n8k16 bf16, fp32 acc, 3-pass hi/lo split).
//   S = sum_h Aa[h,n] * (watt[h]*Ac[h,m]),  F = sum_h Aa[h,n] * (wfc[h]*Ac[h,m])
// Anchor A fragments precomputed (k-independent, g_Apk). Per-k scale+split on
// the C side in smem. Score CTA = 256n x 64m, 512 threads: the C build is
// shared by all 16 n-tiles (halves chip-wide split work vs 128n CTAs).

#define B_ 32
#define N_ 256
#define E_ 300
#define H_ 256
#define K_ 8
#define KSTEPS 19     // ceil(300/16)

// ---------------------------------------------------------------------------
// Device scratch (allocation-free per harness rules)
// ---------------------------------------------------------------------------
__device__ uint32_t g_Apk[B_][16][16][2][32][4];     // [b][ntile][ks][hi/lo][lane][frag]
__device__ float    g_projS[2][B_][256][H_];         // pos/neg proj fp32, [m][h]
__device__ float    g_pnum[2][B_][K_][4];
__device__ float    g_pden[2][B_][K_][4];
__device__ uint32_t g_Wpk[2][2][KSTEPS][256][8];     // [a2h/c2h][hi/lo][ks][h][k/2]

// ---------------------------------------------------------------------------
// Helpers
// ---------------------------------------------------------------------------
__device__ __forceinline__ uint32_t smem_u32(const void* p) {
    uint32_t a;
    asm("{ .reg .u64 t; cvta.to.shared.u64 t, %1; cvt.u32.u64 %0, t; }" : "=r"(a) : "l"(p));
    return a;
}
__device__ __forceinline__ uint32_t cvt2(float v0, float v1) {
    uint32_t r;
    asm("cvt.rn.bf16x2.f32 %0, %1, %2;" : "=r"(r) : "f"(v1), "f"(v0));
    return r;
}
__device__ __forceinline__ void split2(float v0, float v1, uint32_t& uhi, uint32_t& ulo) {
    uhi = cvt2(v0, v1);
    float f0 = __uint_as_float(uhi << 16);
    float f1 = __uint_as_float(uhi & 0xffff0000u);
    ulo = cvt2(v0 - f0, v1 - f1);
}
__device__ __forceinline__ void ldsm4(uint32_t* r, uint32_t addr) {
    asm volatile("ldmatrix.sync.aligned.m8n8.x4.shared.b16 {%0,%1,%2,%3}, [%4];"
        : "=r"(r[0]), "=r"(r[1]), "=r"(r[2]), "=r"(r[3]) : "r"(addr));
}
__device__ __forceinline__ void mma_bf16(float* d, const uint32_t* a,
                                         uint32_t b0, uint32_t b1) {
    asm volatile("mma.sync.aligned.m16n8k16.row.col.f32.bf16.bf16.f32 "
        "{%0,%1,%2,%3}, {%4,%5,%6,%7}, {%8,%9}, {%0,%1,%2,%3};"
        : "+f"(d[0]), "+f"(d[1]), "+f"(d[2]), "+f"(d[3])
        : "r"(a[0]), "r"(a[1]), "r"(a[2]), "r"(a[3]), "r"(b0), "r"(b1));
}
// exp via 2^(x*log2e), deg-5 minimax poly (rel err ~3e-8), FMA-pipe only.
__device__ __forceinline__ float exp_poly(float x) {
    float t = x * 1.4426950408889634f;
    float fi = rintf(t);
    float f = t - fi;
    float p = 0.00133335581f;
    p = fmaf(p, f, 0.00961804886f);
    p = fmaf(p, f, 0.0555041087f);
    p = fmaf(p, f, 0.240226507f);
    p = fmaf(p, f, 0.69314718056f);
    p = fmaf(p, f, 1.0f);
    float s = __int_as_float(((int)fi + 127) << 23);
    return p * s;
}

// ---------------------------------------------------------------------------
// W prep (unchanged)
// ---------------------------------------------------------------------------
__global__ __launch_bounds__(256)
void wprep_kernel(const float* __restrict__ Wa, const float* __restrict__ Wc) {
    const int mode = blockIdx.x & 1, ks = blockIdx.x >> 1;
    const int h = threadIdx.x;
    const float* W = mode ? Wc : Wa;
    const int e0 = ks * 16;
    float v[16];
    #pragma unroll
    for (int j = 0; j < 16; j++)
        v[j] = (e0 + j < E_) ? W[h * E_ + e0 + j] : 0.f;
    #pragma unroll
    for (int i = 0; i < 8; i++) {
        uint32_t hi, lo;
        split2(v[2 * i], v[2 * i + 1], hi, lo);
        g_Wpk[mode][0][ks][h][i] = hi;
        g_Wpk[mode][1][ks][h][i] = lo;
    }
}

// ---------------------------------------------------------------------------
// Projection on HMMA (unchanged from R14).
// ---------------------------------------------------------------------------
#define PSTR 12

__global__ __launch_bounds__(256, 2)
void projmma_kernel(const float* __restrict__ Xa, const float* __restrict__ Xp,
                    const float* __restrict__ Xn,
                    const float* __restrict__ ba, const float* __restrict__ bc) {
    __shared__ uint32_t XH[64 * PSTR], XL[64 * PSTR];
    __shared__ uint32_t WH[256 * PSTR], WL[256 * PSTR];
    __shared__ float bias_s[256];

    const int tid = threadIdx.x, lane = tid & 31, w = tid >> 5;
    const int nq = blockIdx.x;
    const int mb = blockIdx.z;
    const int mode = mb >> 5, b = mb & 31;

    const float* X    = (mode == 0) ? Xa : (mode == 1 ? Xp : Xn);
    const float* bias = (mode == 0) ? ba : bc;
    const int    wsel = (mode == 0) ? 0 : 1;

    bias_s[tid] = bias[tid];

    const float* Xbase = X + ((size_t)b * N_ + nq * 64) * E_;
    const int warp_n = w & 3, warp_h = w >> 2;

    const uint32_t xhb = smem_u32(XH), xlb = smem_u32(XL);
    const uint32_t whb = smem_u32(WH), wlb = smem_u32(WL);

    const uint32_t a_off = (uint32_t)(warp_n * 16 + (lane & 15)) * 48 + ((lane >> 4) << 4);
    const uint32_t c_off = (uint32_t)((lane & 7) + ((lane >> 4) << 3)) * 48
                         + (((lane >> 3) & 1) << 4);

    const int fx_n = tid >> 2, fx_q = tid & 3;

    float acc[16][4];
    #pragma unroll
    for (int i = 0; i < 16; i++)
        #pragma unroll
        for (int j = 0; j < 4; j++) acc[i][j] = 0.f;

    for (int ks = 0; ks < KSTEPS; ks++) {
        const int e0 = ks * 16;
        __syncthreads();

        {
            float4 v = make_float4(0.f, 0.f, 0.f, 0.f);
            if (e0 + fx_q * 4 < E_)
                v = *(const float4*)(Xbase + fx_n * E_ + e0 + fx_q * 4);
            uint32_t h0, l0, h1, l1;
            split2(v.x, v.y, h0, l0);
            split2(v.z, v.w, h1, l1);
            const int o = fx_n * PSTR + fx_q * 2;
            XH[o] = h0; XH[o + 1] = h1;
            XL[o] = l0; XL[o + 1] = l1;
        }
        #pragma unroll
        for (int i = 0; i < 4; i++) {
            int idx = tid + i * 256;
            int var = idx >> 9, rem = idx & 511;
            int h = rem >> 1, half = rem & 1;
            uint4 v = *(const uint4*)&g_Wpk[wsel][var][ks][h][half * 4];
            uint32_t* dst = (var ? WL : WH) + h * PSTR + half * 4;
            *(uint4*)dst = v;
        }
        __syncthreads();

        uint32_t aH[4], aL[4];
        ldsm4(aH, xhb + a_off);
        ldsm4(aL, xlb + a_off);
        #pragma unroll
        for (int qh = 0; qh < 4; qh++) {
            const uint32_t hb = (uint32_t)(warp_h * 128 + qh * 32) * 48;
            uint32_t bh[8], bl[8];
            ldsm4(bh + 0, whb + hb + c_off);
            ldsm4(bh + 4, whb + hb + 16 * 48 + c_off);
            ldsm4(bl + 0, wlb + hb + c_off);
            ldsm4(bl + 4, wlb + hb + 16 * 48 + c_off);
            #pragma unroll
            for (int t2 = 0; t2 < 4; t2++) {
                const int ht = qh * 4 + t2;
                mma_bf16(acc[ht], aH, bh[2 * t2], bh[2 * t2 + 1]);
                mma_bf16(acc[ht], aL, bh[2 * t2], bh[2 * t2 + 1]);
                mma_bf16(acc[ht], aH, bl[2 * t2], bl[2 * t2 + 1]);
            }
        }
    }

    const int g = lane >> 2, q = lane & 3;
    if (mode == 0) {
        const int nt = nq * 4 + warp_n;
        #pragma unroll
        for (int ht2 = 0; ht2 < 8; ht2++) {
            const int ks = warp_h * 8 + ht2;
            const int he = 2 * ht2, ho = he + 1;
            const int hbe = warp_h * 128 + he * 8 + 2 * q;
            const int hbo = hbe + 8;
            uint32_t fh[4], fl[4];
            split2(acc[he][0] + bias_s[hbe], acc[he][1] + bias_s[hbe + 1], fh[0], fl[0]);
            split2(acc[he][2] + bias_s[hbe], acc[he][3] + bias_s[hbe + 1], fh[1], fl[1]);
            split2(acc[ho][0] + bias_s[hbo], acc[ho][1] + bias_s[hbo + 1], fh[2], fl[2]);
            split2(acc[ho][2] + bias_s[hbo], acc[ho][3] + bias_s[hbo + 1], fh[3], fl[3]);
            *(uint4*)&g_Apk[b][nt][ks][0][lane][0] = *(uint4*)fh;
            *(uint4*)&g_Apk[b][nt][ks][1][lane][0] = *(uint4*)fl;
        }
    } else {
        const int side = mode - 1;
        const int n0 = nq * 64 + warp_n * 16 + g;
        #pragma unroll
        for (int ht = 0; ht < 16; ht++) {
            const int h = warp_h * 128 + ht * 8 + 2 * q;
            const float b0 = bias_s[h], b1 = bias_s[h + 1];
            *(float2*)&g_projS[side][b][n0][h]     = make_float2(acc[ht][0] + b0, acc[ht][1] + b1);
            *(float2*)&g_projS[side][b][n0 + 8][h] = make_float2(acc[ht][2] + b0, acc[ht][3] + b1);
        }
    }
}

// ---------------------------------------------------------------------------
// Score: CTA = 256n x 64m of one (k, b, side). bx = k + 8*mq. 512 threads.
// Warp w (0..15) = n-tile w: rows [16w, 16w+16), all 64 m.
// A: ready fragments from g_Apk (2x LDG.128 per ks, no ALU).
// C: 4 smem variants (S-hi/lo, F-hi/lo) built once per h-chunk by 512 threads.
// ---------------------------------------------------------------------------
#define ASTR 20   // u32 row stride (80 B, conflict-free)

__global__ __launch_bounds__(512, 1)
void score_kernel(const float* __restrict__ W_att, const float* __restrict__ W_fc) {
    __shared__ uint32_t CSh[64 * ASTR], CSl[64 * ASTR];
    __shared__ uint32_t CFh[64 * ASTR], CFl[64 * ASTR];
    __shared__ float watt_s[H_], wfc_s[H_];
    __shared__ float rn[16], rd[16];

    const int tid  = threadIdx.x;
    const int lane = tid & 31, w = tid >> 5;   // w = 0..15 = n-tile
    const int k  = blockIdx.x & 7;
    const int mq = blockIdx.x >> 3;
    const int b = blockIdx.y, side = blockIdx.z;

    if (tid < H_) {
        watt_s[tid] = W_att[k * H_ + tid];
        wfc_s [tid] = W_fc [k * H_ + tid];
    }

    const float* Cs = &g_projS[side][b][0][0];
    const uint32_t cSh = smem_u32(CSh), cSl = smem_u32(CSl);
    const uint32_t cFh = smem_u32(CFh), cFl = smem_u32(CFl);

    const uint32_t c_off = (uint32_t)((lane & 7) + ((lane >> 4) << 3)) * (ASTR * 4)
                         + (((lane >> 3) & 1) << 4);

    // C-build decomposition: thread -> m = tid>>3 (0..63), h-quad hq = tid&7
    const int cb_m = tid >> 3, cb_hq = tid & 7;
    const float* cb_src = Cs + (size_t)(mq * 64 + cb_m) * H_ + cb_hq * 4;
    const int cb_o = cb_m * ASTR + cb_hq * 2;

    float accS[2][4][4], accF[2][4][4];
    #pragma unroll
    for (int mh = 0; mh < 2; mh++)
        #pragma unroll
        for (int gg = 0; gg < 4; gg++)
            #pragma unroll
            for (int r = 0; r < 4; r++) { accS[mh][gg][r] = 0.f; accF[mh][gg][r] = 0.f; }

    for (int hc = 0; hc < 8; hc++) {
        const int h0 = hc * 32;
        __syncthreads();   // previous chunk's ldsm reads done (covers watt_s 1st pass)

        // ---- C build: 64m x 32h x {S,F}, scale + hi/lo split (4 split2/thread)
        {
            float4 v  = *(const float4*)(cb_src + h0);
            float4 wa = *(const float4*)(watt_s + h0 + cb_hq * 4);
            float4 wf = *(const float4*)(wfc_s  + h0 + cb_hq * 4);
            uint32_t h0a, l0a, h1a, l1a;
            split2(wa.x * v.x, wa.y * v.y, h0a, l0a);
            split2(wa.z * v.z, wa.w * v.w, h1a, l1a);
            *(uint2*)&CSh[cb_o] = make_uint2(h0a, h1a);
            *(uint2*)&CSl[cb_o] = make_uint2(l0a, l1a);
            split2(wf.x * v.x, wf.y * v.y, h0a, l0a);
            split2(wf.z * v.z, wf.w * v.w, h1a, l1a);
            *(uint2*)&CFh[cb_o] = make_uint2(h0a, h1a);
            *(uint2*)&CFl[cb_o] = make_uint2(l0a, l1a);
        }
        __syncthreads();   // build visible

        #pragma unroll
        for (int ks = 0; ks < 2; ks++) {
            const int ksg = hc * 2 + ks;
            uint32_t aH[4], aL[4];
            *(uint4*)aH = *(const uint4*)&g_Apk[b][w][ksg][0][lane][0];
            *(uint4*)aL = *(const uint4*)&g_Apk[b][w][ksg][1][lane][0];

            const uint32_t hkb = (uint32_t)(ks * 32);
            #pragma unroll
            for (int mh = 0; mh < 2; mh++) {
                const uint32_t mrow = (uint32_t)(mh * 32) * (ASTR * 4);
                uint32_t c[8];
                // S hi
                ldsm4(c + 0, cSh + mrow + c_off + hkb);
                ldsm4(c + 4, cSh + mrow + 16 * ASTR * 4 + c_off + hkb);
                #pragma unroll
                for (int gg = 0; gg < 4; gg++) {
                    mma_bf16(accS[mh][gg], aH, c[2*gg], c[2*gg+1]);
                    mma_bf16(accS[mh][gg], aL, c[2*gg], c[2*gg+1]);
                }
                // S lo
                ldsm4(c + 0, cSl + mrow + c_off + hkb);
                ldsm4(c + 4, cSl + mrow + 16 * ASTR * 4 + c_off + hkb);
                #pragma unroll
                for (int gg = 0; gg < 4; gg++)
                    mma_bf16(accS[mh][gg], aH, c[2*gg], c[2*gg+1]);
                // F hi
                ldsm4(c + 0, cFh + mrow + c_off + hkb);
                ldsm4(c + 4, cFh + mrow + 16 * ASTR * 4 + c_off + hkb);
                #pragma unroll
                for (int gg = 0; gg < 4; gg++) {
                    mma_bf16(accF[mh][gg], aH, c[2*gg], c[2*gg+1]);
                    mma_bf16(accF[mh][gg], aL, c[2*gg], c[2*gg+1]);
                }
                // F lo
                ldsm4(c + 0, cFl + mrow + c_off + hkb);
                ldsm4(c + 4, cFl + mrow + 16 * ASTR * 4 + c_off + hkb);
                #pragma unroll
                for (int gg = 0; gg < 4; gg++)
                    mma_bf16(accF[mh][gg], aH, c[2*gg], c[2*gg+1]);
            }
        }
    }

    // ---- epilogue: hybrid exp (even -> MUFU EX2, odd -> FMA-pipe poly)
    float num = 0.f, den = 0.f;
    #pragma unroll
    for (int mh = 0; mh < 2; mh++)
        #pragma unroll
        for (int gg = 0; gg < 4; gg++)
            #pragma unroll
            for (int r = 0; r < 4; r++) {
                float S = accS[mh][gg][r];
                float e = (r & 1) ? exp_poly(S) : __expf(S);
                den += e;
                num = fmaf(e, accF[mh][gg][r], num);
            }

    #pragma unroll
    for (int o = 16; o; o >>= 1) {
        num += __shfl_down_sync(0xffffffffu, num, o);
        den += __shfl_down_sync(0xffffffffu, den, o);
    }
    if (lane == 0) { rn[w] = num; rd[w] = den; }
    __syncthreads();
    if (tid == 0) {
        float sn = 0.f, sd = 0.f;
        #pragma unroll
        for (int q = 0; q < 16; q++) { sn += rn[q]; sd += rd[q]; }
        g_pnum[side][b][k][mq] = sn;
        g_pden[side][b][k][mq] = sd;
    }
}

// ---------------------------------------------------------------------------
// Finalize: loss = mean_b relu(score_n - score_p + margin). 256 threads.
// ---------------------------------------------------------------------------
__global__ void finalize_kernel(float* __restrict__ out) {
    __shared__ float sc[8][32];
    const int lane = threadIdx.x & 31;   // = b
    const int w    = threadIdx.x >> 5;
    float s = 0.f;
    #pragma unroll
    for (int pi = 0; pi < 2; pi++) {
        int p = w * 2 + pi;
        int side = p >> 3, k = p & 7;
        float n = 0.f, d = 0.f;
        #pragma unroll
        for (int q = 0; q < 4; q++) {
            n += g_pnum[side][lane][k][q];
            d += g_pden[side][lane][k][q];
        }
        float v = n / d;
        s += side ? v : -v;
    }
    sc[w][lane] = s;
    __syncthreads();
    if (w == 0) {
        float tot = 0.f;
        #pragma unroll
        for (int ww = 0; ww < 8; ww++) tot += sc[ww][lane];
        float v = fmaxf(tot + 0.2f, 0.f);
        #pragma unroll
        for (int o = 16; o; o >>= 1) v += __shfl_down_sync(0xffffffffu, v, o);
        if (lane == 0) out[0] = v * (1.0f / B_);
    }
}

// ---------------------------------------------------------------------------
extern "C" void kernel_launch(void* const* d_in, const int* in_sizes, int n_in,
                              void* d_out, int out_size) {
    const float* he_anchor = (const float*)d_in[0];
    const float* he_pos    = (const float*)d_in[1];
    const float* he_neg    = (const float*)d_in[2];
    const float* W_a2h     = (const float*)d_in[3];
    const float* b_a2h     = (const float*)d_in[4];
    const float* W_c2h     = (const float*)d_in[5];
    const float* b_c2h     = (const float*)d_in[6];
    const float* W_att     = (const float*)d_in[7];
    // d_in[8] = b_att : cancels in softmax
    const float* W_fc      = (const float*)d_in[9];
    // d_in[10] = b_fc : cancels in score difference

    wprep_kernel<<<2 * KSTEPS, 256>>>(W_a2h, W_c2h);

    projmma_kernel<<<dim3(4, 1, 96), 256>>>(he_anchor, he_pos, he_neg,
                                            b_a2h, b_c2h);

    score_kernel<<<dim3(32, B_, 2), 512>>>(W_att, W_fc);

    finalize_kernel<<<1, 256>>>((float*)d_out);
}

// round 16
// speedup vs baseline: 1.2954x; 1.0684x over previous
#include <cuda_runtime.h>
#include <cuda_bf16.h>
#include <cstdint>

// HGAN triplet loss. Projections and score bilinear forms on HMMA
// (mma.sync m16n8k16 bf16, fp32 acc, 3-pass hi/lo split).
//   S = sum_h Aa[h,n] * (watt[h]*Ac[h,m]),  F = sum_h Aa[h,n] * (wfc[h]*Ac[h,m])
// Anchor A fragments precomputed (k-independent, g_Apk). Per-k scale+split on
// the C side in smem. Score CTA = 256n x 64m, 512 threads. C built in 64h
// super-chunks, double-buffered: ONE barrier per super-chunk (4 total).

#define B_ 32
#define N_ 256
#define E_ 300
#define H_ 256
#define K_ 8
#define KSTEPS 19     // ceil(300/16)

// ---------------------------------------------------------------------------
// Device scratch (allocation-free per harness rules)
// ---------------------------------------------------------------------------
__device__ uint32_t g_Apk[B_][16][16][2][32][4];     // [b][ntile][ks][hi/lo][lane][frag]
__device__ float    g_projS[2][B_][256][H_];         // pos/neg proj fp32, [m][h]
__device__ float    g_pnum[2][B_][K_][4];
__device__ float    g_pden[2][B_][K_][4];
__device__ uint32_t g_Wpk[2][2][KSTEPS][256][8];     // [a2h/c2h][hi/lo][ks][h][k/2]

// ---------------------------------------------------------------------------
// Helpers
// ---------------------------------------------------------------------------
__device__ __forceinline__ uint32_t smem_u32(const void* p) {
    uint32_t a;
    asm("{ .reg .u64 t; cvta.to.shared.u64 t, %1; cvt.u32.u64 %0, t; }" : "=r"(a) : "l"(p));
    return a;
}
__device__ __forceinline__ uint32_t cvt2(float v0, float v1) {
    uint32_t r;
    asm("cvt.rn.bf16x2.f32 %0, %1, %2;" : "=r"(r) : "f"(v1), "f"(v0));
    return r;
}
__device__ __forceinline__ void split2(float v0, float v1, uint32_t& uhi, uint32_t& ulo) {
    uhi = cvt2(v0, v1);
    float f0 = __uint_as_float(uhi << 16);
    float f1 = __uint_as_float(uhi & 0xffff0000u);
    ulo = cvt2(v0 - f0, v1 - f1);
}
__device__ __forceinline__ void ldsm4(uint32_t* r, uint32_t addr) {
    asm volatile("ldmatrix.sync.aligned.m8n8.x4.shared.b16 {%0,%1,%2,%3}, [%4];"
        : "=r"(r[0]), "=r"(r[1]), "=r"(r[2]), "=r"(r[3]) : "r"(addr));
}
__device__ __forceinline__ void mma_bf16(float* d, const uint32_t* a,
                                         uint32_t b0, uint32_t b1) {
    asm volatile("mma.sync.aligned.m16n8k16.row.col.f32.bf16.bf16.f32 "
        "{%0,%1,%2,%3}, {%4,%5,%6,%7}, {%8,%9}, {%0,%1,%2,%3};"
        : "+f"(d[0]), "+f"(d[1]), "+f"(d[2]), "+f"(d[3])
        : "r"(a[0]), "r"(a[1]), "r"(a[2]), "r"(a[3]), "r"(b0), "r"(b1));
}
// exp via 2^(x*log2e), deg-5 minimax poly (rel err ~3e-8), FMA-pipe only.
__device__ __forceinline__ float exp_poly(float x) {
    float t = x * 1.4426950408889634f;
    float fi = rintf(t);
    float f = t - fi;
    float p = 0.00133335581f;
    p = fmaf(p, f, 0.00961804886f);
    p = fmaf(p, f, 0.0555041087f);
    p = fmaf(p, f, 0.240226507f);
    p = fmaf(p, f, 0.69314718056f);
    p = fmaf(p, f, 1.0f);
    float s = __int_as_float(((int)fi + 127) << 23);
    return p * s;
}

// ---------------------------------------------------------------------------
// W prep (unchanged)
// ---------------------------------------------------------------------------
__global__ __launch_bounds__(256)
void wprep_kernel(const float* __restrict__ Wa, const float* __restrict__ Wc) {
    const int mode = blockIdx.x & 1, ks = blockIdx.x >> 1;
    const int h = threadIdx.x;
    const float* W = mode ? Wc : Wa;
    const int e0 = ks * 16;
    float v[16];
    #pragma unroll
    for (int j = 0; j < 16; j++)
        v[j] = (e0 + j < E_) ? W[h * E_ + e0 + j] : 0.f;
    #pragma unroll
    for (int i = 0; i < 8; i++) {
        uint32_t hi, lo;
        split2(v[2 * i], v[2 * i + 1], hi, lo);
        g_Wpk[mode][0][ks][h][i] = hi;
        g_Wpk[mode][1][ks][h][i] = lo;
    }
}

// ---------------------------------------------------------------------------
// Projection on HMMA (unchanged from R14/R15)
// ---------------------------------------------------------------------------
#define PSTR 12

__global__ __launch_bounds__(256, 2)
void projmma_kernel(const float* __restrict__ Xa, const float* __restrict__ Xp,
                    const float* __restrict__ Xn,
                    const float* __restrict__ ba, const float* __restrict__ bc) {
    __shared__ uint32_t XH[64 * PSTR], XL[64 * PSTR];
    __shared__ uint32_t WH[256 * PSTR], WL[256 * PSTR];
    __shared__ float bias_s[256];

    const int tid = threadIdx.x, lane = tid & 31, w = tid >> 5;
    const int nq = blockIdx.x;
    const int mb = blockIdx.z;
    const int mode = mb >> 5, b = mb & 31;

    const float* X    = (mode == 0) ? Xa : (mode == 1 ? Xp : Xn);
    const float* bias = (mode == 0) ? ba : bc;
    const int    wsel = (mode == 0) ? 0 : 1;

    bias_s[tid] = bias[tid];

    const float* Xbase = X + ((size_t)b * N_ + nq * 64) * E_;
    const int warp_n = w & 3, warp_h = w >> 2;

    const uint32_t xhb = smem_u32(XH), xlb = smem_u32(XL);
    const uint32_t whb = smem_u32(WH), wlb = smem_u32(WL);

    const uint32_t a_off = (uint32_t)(warp_n * 16 + (lane & 15)) * 48 + ((lane >> 4) << 4);
    const uint32_t c_off = (uint32_t)((lane & 7) + ((lane >> 4) << 3)) * 48
                         + (((lane >> 3) & 1) << 4);

    const int fx_n = tid >> 2, fx_q = tid & 3;

    float acc[16][4];
    #pragma unroll
    for (int i = 0; i < 16; i++)
        #pragma unroll
        for (int j = 0; j < 4; j++) acc[i][j] = 0.f;

    for (int ks = 0; ks < KSTEPS; ks++) {
        const int e0 = ks * 16;
        __syncthreads();

        {
            float4 v = make_float4(0.f, 0.f, 0.f, 0.f);
            if (e0 + fx_q * 4 < E_)
                v = *(const float4*)(Xbase + fx_n * E_ + e0 + fx_q * 4);
            uint32_t h0, l0, h1, l1;
            split2(v.x, v.y, h0, l0);
            split2(v.z, v.w, h1, l1);
            const int o = fx_n * PSTR + fx_q * 2;
            XH[o] = h0; XH[o + 1] = h1;
            XL[o] = l0; XL[o + 1] = l1;
        }
        #pragma unroll
        for (int i = 0; i < 4; i++) {
            int idx = tid + i * 256;
            int var = idx >> 9, rem = idx & 511;
            int h = rem >> 1, half = rem & 1;
            uint4 v = *(const uint4*)&g_Wpk[wsel][var][ks][h][half * 4];
            uint32_t* dst = (var ? WL : WH) + h * PSTR + half * 4;
            *(uint4*)dst = v;
        }
        __syncthreads();

        uint32_t aH[4], aL[4];
        ldsm4(aH, xhb + a_off);
        ldsm4(aL, xlb + a_off);
        #pragma unroll
        for (int qh = 0; qh < 4; qh++) {
            const uint32_t hb = (uint32_t)(warp_h * 128 + qh * 32) * 48;
            uint32_t bh[8], bl[8];
            ldsm4(bh + 0, whb + hb + c_off);
            ldsm4(bh + 4, whb + hb + 16 * 48 + c_off);
            ldsm4(bl + 0, wlb + hb + c_off);
            ldsm4(bl + 4, wlb + hb + 16 * 48 + c_off);
            #pragma unroll
            for (int t2 = 0; t2 < 4; t2++) {
                const int ht = qh * 4 + t2;
                mma_bf16(acc[ht], aH, bh[2 * t2], bh[2 * t2 + 1]);
                mma_bf16(acc[ht], aL, bh[2 * t2], bh[2 * t2 + 1]);
                mma_bf16(acc[ht], aH, bl[2 * t2], bl[2 * t2 + 1]);
            }
        }
    }

    const int g = lane >> 2, q = lane & 3;
    if (mode == 0) {
        const int nt = nq * 4 + warp_n;
        #pragma unroll
        for (int ht2 = 0; ht2 < 8; ht2++) {
            const int ks = warp_h * 8 + ht2;
            const int he = 2 * ht2, ho = he + 1;
            const int hbe = warp_h * 128 + he * 8 + 2 * q;
            const int hbo = hbe + 8;
            uint32_t fh[4], fl[4];
            split2(acc[he][0] + bias_s[hbe], acc[he][1] + bias_s[hbe + 1], fh[0], fl[0]);
            split2(acc[he][2] + bias_s[hbe], acc[he][3] + bias_s[hbe + 1], fh[1], fl[1]);
            split2(acc[ho][0] + bias_s[hbo], acc[ho][1] + bias_s[hbo + 1], fh[2], fl[2]);
            split2(acc[ho][2] + bias_s[hbo], acc[ho][3] + bias_s[hbo + 1], fh[3], fl[3]);
            *(uint4*)&g_Apk[b][nt][ks][0][lane][0] = *(uint4*)fh;
            *(uint4*)&g_Apk[b][nt][ks][1][lane][0] = *(uint4*)fl;
        }
    } else {
        const int side = mode - 1;
        const int n0 = nq * 64 + warp_n * 16 + g;
        #pragma unroll
        for (int ht = 0; ht < 16; ht++) {
            const int h = warp_h * 128 + ht * 8 + 2 * q;
            const float b0 = bias_s[h], b1 = bias_s[h + 1];
            *(float2*)&g_projS[side][b][n0][h]     = make_float2(acc[ht][0] + b0, acc[ht][1] + b1);
            *(float2*)&g_projS[side][b][n0 + 8][h] = make_float2(acc[ht][2] + b0, acc[ht][3] + b1);
        }
    }
}

// ---------------------------------------------------------------------------
// Score: CTA = 256n x 64m of one (k, b, side). bx = k + 8*mq. 512 threads.
// Warp w (0..15) = n-tile w. C built in 64h super-chunks (4 ks each),
// double-buffered: build(sc+1) issued before mma(sc); ONE barrier per chunk.
// ---------------------------------------------------------------------------
#define CSTR 36   // u32 row stride for 64h rows (144 B; 4i mod 32 bank walk)
#define CB_VAR (64 * CSTR)                 // u32 per variant
#define SC_SMEM (2 * 4 * CB_VAR * 4 + 2048 + 256)

__global__ __launch_bounds__(512, 1)
void score_kernel(const float* __restrict__ W_att, const float* __restrict__ W_fc) {
    extern __shared__ uint32_t dsm[];
    // layout: Cb[2][4][CB_VAR] | watt_s[256] | wfc_s[256] | rn[16] | rd[16]
    uint32_t* Cb = dsm;
    float* watt_s = (float*)(dsm + 2 * 4 * CB_VAR);
    float* wfc_s  = watt_s + 256;
    float* rn     = wfc_s + 256;
    float* rd     = rn + 16;

    const int tid  = threadIdx.x;
    const int lane = tid & 31, w = tid >> 5;   // w = 0..15 = n-tile
    const int k  = blockIdx.x & 7;
    const int mq = blockIdx.x >> 3;
    const int b = blockIdx.y, side = blockIdx.z;

    if (tid < H_) {
        watt_s[tid] = W_att[k * H_ + tid];
        wfc_s [tid] = W_fc [k * H_ + tid];
    }

    const float* Cs = &g_projS[side][b][0][0];
    const uint32_t cb_base = smem_u32(Cb);

    const uint32_t c_off = (uint32_t)((lane & 7) + ((lane >> 4) << 3)) * (CSTR * 4)
                         + (((lane >> 3) & 1) << 4);

    // C-build decomposition: thread -> m = tid>>3 (0..63), h-octet hq = tid&7
    const int cb_m = tid >> 3, cb_hq = tid & 7;
    const float* cb_src = Cs + (size_t)(mq * 64 + cb_m) * H_ + cb_hq * 8;
    const int cb_o = cb_m * CSTR + cb_hq * 4;

    float accS[2][4][4], accF[2][4][4];
    #pragma unroll
    for (int mh = 0; mh < 2; mh++)
        #pragma unroll
        for (int gg = 0; gg < 4; gg++)
            #pragma unroll
            for (int r = 0; r < 4; r++) { accS[mh][gg][r] = 0.f; accF[mh][gg][r] = 0.f; }

    __syncthreads();   // watt_s/wfc_s visible

    // ---- build(sc, buf): scale + split 64m x 64h into buffer buf
    #define BUILD(sc_, buf_) do {                                              \
        const float* s_ = cb_src + (sc_) * 64;                                 \
        const int hh_ = (sc_) * 64 + cb_hq * 8;                                \
        float4 v0 = *(const float4*)(s_);                                      \
        float4 v1 = *(const float4*)(s_ + 4);                                  \
        float4 wa0 = *(const float4*)(watt_s + hh_);                           \
        float4 wa1 = *(const float4*)(watt_s + hh_ + 4);                       \
        float4 wf0 = *(const float4*)(wfc_s + hh_);                            \
        float4 wf1 = *(const float4*)(wfc_s + hh_ + 4);                        \
        uint32_t* base_ = Cb + (buf_) * 4 * CB_VAR;                            \
        uint32_t h0,l0,h1,l1,h2,l2,h3,l3;                                      \
        split2(wa0.x*v0.x, wa0.y*v0.y, h0, l0);                                \
        split2(wa0.z*v0.z, wa0.w*v0.w, h1, l1);                                \
        split2(wa1.x*v1.x, wa1.y*v1.y, h2, l2);                                \
        split2(wa1.z*v1.z, wa1.w*v1.w, h3, l3);                                \
        *(uint4*)&base_[0 * CB_VAR + cb_o] = make_uint4(h0, h1, h2, h3);       \
        *(uint4*)&base_[1 * CB_VAR + cb_o] = make_uint4(l0, l1, l2, l3);       \
        split2(wf0.x*v0.x, wf0.y*v0.y, h0, l0);                                \
        split2(wf0.z*v0.z, wf0.w*v0.w, h1, l1);                                \
        split2(wf1.x*v1.x, wf1.y*v1.y, h2, l2);                                \
        split2(wf1.z*v1.z, wf1.w*v1.w, h3, l3);                                \
        *(uint4*)&base_[2 * CB_VAR + cb_o] = make_uint4(h0, h1, h2, h3);       \
        *(uint4*)&base_[3 * CB_VAR + cb_o] = make_uint4(l0, l1, l2, l3);       \
    } while (0)

    BUILD(0, 0);
    __syncthreads();

    for (int sc = 0; sc < 4; sc++) {
        const int buf = sc & 1;
        if (sc < 3) BUILD(sc + 1, buf ^ 1);   // overlaps with mma below

        const uint32_t cSh = cb_base + (uint32_t)(buf * 4 + 0) * CB_VAR * 4;
        const uint32_t cSl = cb_base + (uint32_t)(buf * 4 + 1) * CB_VAR * 4;
        const uint32_t cFh = cb_base + (uint32_t)(buf * 4 + 2) * CB_VAR * 4;
        const uint32_t cFl = cb_base + (uint32_t)(buf * 4 + 3) * CB_VAR * 4;

        #pragma unroll
        for (int ksl = 0; ksl < 4; ksl++) {
            const int ksg = sc * 4 + ksl;
            uint32_t aH[4], aL[4];
            *(uint4*)aH = *(const uint4*)&g_Apk[b][w][ksg][0][lane][0];
            *(uint4*)aL = *(const uint4*)&g_Apk[b][w][ksg][1][lane][0];

            const uint32_t hkb = (uint32_t)(ksl * 32);
            #pragma unroll
            for (int mh = 0; mh < 2; mh++) {
                const uint32_t mrow = (uint32_t)(mh * 32) * (CSTR * 4);
                uint32_t c[8];
                // S hi
                ldsm4(c + 0, cSh + mrow + c_off + hkb);
                ldsm4(c + 4, cSh + mrow + 16 * CSTR * 4 + c_off + hkb);
                #pragma unroll
                for (int gg = 0; gg < 4; gg++) {
                    mma_bf16(accS[mh][gg], aH, c[2*gg], c[2*gg+1]);
                    mma_bf16(accS[mh][gg], aL, c[2*gg], c[2*gg+1]);
                }
                // S lo
                ldsm4(c + 0, cSl + mrow + c_off + hkb);
                ldsm4(c + 4, cSl + mrow + 16 * CSTR * 4 + c_off + hkb);
                #pragma unroll
                for (int gg = 0; gg < 4; gg++)
                    mma_bf16(accS[mh][gg], aH, c[2*gg], c[2*gg+1]);
                // F hi
                ldsm4(c + 0, cFh + mrow + c_off + hkb);
                ldsm4(c + 4, cFh + mrow + 16 * CSTR * 4 + c_off + hkb);
                #pragma unroll
                for (int gg = 0; gg < 4; gg++) {
                    mma_bf16(accF[mh][gg], aH, c[2*gg], c[2*gg+1]);
                    mma_bf16(accF[mh][gg], aL, c[2*gg], c[2*gg+1]);
                }
                // F lo
                ldsm4(c + 0, cFl + mrow + c_off + hkb);
                ldsm4(c + 4, cFl + mrow + 16 * CSTR * 4 + c_off + hkb);
                #pragma unroll
                for (int gg = 0; gg < 4; gg++)
                    mma_bf16(accF[mh][gg], aH, c[2*gg], c[2*gg+1]);
            }
        }
        __syncthreads();   // mma(sc) done; next iter may overwrite buf^1
    }

    // ---- epilogue: hybrid exp (even -> MUFU EX2, odd -> FMA-pipe poly)
    float num = 0.f, den = 0.f;
    #pragma unroll
    for (int mh = 0; mh < 2; mh++)
        #pragma unroll
        for (int gg = 0; gg < 4; gg++)
            #pragma unroll
            for (int r = 0; r < 4; r++) {
                float S = accS[mh][gg][r];
                float e = (r & 1) ? exp_poly(S) : __expf(S);
                den += e;
                num = fmaf(e, accF[mh][gg][r], num);
            }

    #pragma unroll
    for (int o = 16; o; o >>= 1) {
        num += __shfl_down_sync(0xffffffffu, num, o);
        den += __shfl_down_sync(0xffffffffu, den, o);
    }
    if (lane == 0) { rn[w] = num; rd[w] = den; }
    __syncthreads();
    if (tid == 0) {
        float sn = 0.f, sd = 0.f;
        #pragma unroll
        for (int q = 0; q < 16; q++) { sn += rn[q]; sd += rd[q]; }
        g_pnum[side][b][k][mq] = sn;
        g_pden[side][b][k][mq] = sd;
    }
}

// ---------------------------------------------------------------------------
// Finalize: loss = mean_b relu(score_n - score_p + margin). 256 threads.
// ---------------------------------------------------------------------------
__global__ void finalize_kernel(float* __restrict__ out) {
    __shared__ float sc[8][32];
    const int lane = threadIdx.x & 31;   // = b
    const int w    = threadIdx.x >> 5;
    float s = 0.f;
    #pragma unroll
    for (int pi = 0; pi < 2; pi++) {
        int p = w * 2 + pi;
        int side = p >> 3, k = p & 7;
        float n = 0.f, d = 0.f;
        #pragma unroll
        for (int q = 0; q < 4; q++) {
            n += g_pnum[side][lane][k][q];
            d += g_pden[side][lane][k][q];
        }
        float v = n / d;
        s += side ? v : -v;
    }
    sc[w][lane] = s;
    __syncthreads();
    if (w == 0) {
        float tot = 0.f;
        #pragma unroll
        for (int ww = 0; ww < 8; ww++) tot += sc[ww][lane];
        float v = fmaxf(tot + 0.2f, 0.f);
        #pragma unroll
        for (int o = 16; o; o >>= 1) v += __shfl_down_sync(0xffffffffu, v, o);
        if (lane == 0) out[0] = v * (1.0f / B_);
    }
}

// ---------------------------------------------------------------------------
extern "C" void kernel_launch(void* const* d_in, const int* in_sizes, int n_in,
                              void* d_out, int out_size) {
    const float* he_anchor = (const float*)d_in[0];
    const float* he_pos    = (const float*)d_in[1];
    const float* he_neg    = (const float*)d_in[2];
    const float* W_a2h     = (const float*)d_in[3];
    const float* b_a2h     = (const float*)d_in[4];
    const float* W_c2h     = (const float*)d_in[5];
    const float* b_c2h     = (const float*)d_in[6];
    const float* W_att     = (const float*)d_in[7];
    // d_in[8] = b_att : cancels in softmax
    const float* W_fc      = (const float*)d_in[9];
    // d_in[10] = b_fc : cancels in score difference

    cudaFuncSetAttribute(score_kernel,
                         cudaFuncAttributeMaxDynamicSharedMemorySize, SC_SMEM);

    wprep_kernel<<<2 * KSTEPS, 256>>>(W_a2h, W_c2h);

    projmma_kernel<<<dim3(4, 1, 96), 256>>>(he_anchor, he_pos, he_neg,
                                            b_a2h, b_c2h);

    score_kernel<<<dim3(32, B_, 2), 512, SC_SMEM>>>(W_att, W_fc);

    finalize_kernel<<<1, 256>>>((float*)d_out);
}

// round 17
// speedup vs baseline: 1.5818x; 1.2211x over previous
#include <cuda_runtime.h>
#include <cuda_bf16.h>
#include <cuda_fp16.h>
#include <cstdint>

// HGAN triplet loss. Projections on bf16 HMMA (3-pass split, unchanged);
// score bilinear forms on fp16 HMMA with a 2-pass split:
//   A (anchor) = exact fp16 (hi + lo) pair, C = single fp16 of (w*c).
//   Dropped term ~2^-11 relative -> loss rel_err ~1e-5 (tolerance 1e-3).
// Score CTA = 256n x 64m, 512 threads, 64h super-chunks, double-buffered
// C build, one barrier per super-chunk.

#define B_ 32
#define N_ 256
#define E_ 300
#define H_ 256
#define K_ 8
#define KSTEPS 19     // ceil(300/16)

// ---------------------------------------------------------------------------
// Device scratch (allocation-free per harness rules)
// ---------------------------------------------------------------------------
__device__ uint32_t g_Apk[B_][16][16][2][32][4];     // fp16 A frags [b][nt][ks][hi/lo][lane][4]
__device__ float    g_projS[2][B_][256][H_];         // pos/neg proj fp32, [m][h]
__device__ float    g_pnum[2][B_][K_][4];
__device__ float    g_pden[2][B_][K_][4];
__device__ uint32_t g_Wpk[2][2][KSTEPS][256][8];     // bf16 W pack (projmma)

// ---------------------------------------------------------------------------
// Helpers
// ---------------------------------------------------------------------------
__device__ __forceinline__ uint32_t smem_u32(const void* p) {
    uint32_t a;
    asm("{ .reg .u64 t; cvta.to.shared.u64 t, %1; cvt.u32.u64 %0, t; }" : "=r"(a) : "l"(p));
    return a;
}
// ---- bf16 (projection path) ----
__device__ __forceinline__ uint32_t cvt2(float v0, float v1) {
    uint32_t r;
    asm("cvt.rn.bf16x2.f32 %0, %1, %2;" : "=r"(r) : "f"(v1), "f"(v0));
    return r;
}
__device__ __forceinline__ void split2(float v0, float v1, uint32_t& uhi, uint32_t& ulo) {
    uhi = cvt2(v0, v1);
    float f0 = __uint_as_float(uhi << 16);
    float f1 = __uint_as_float(uhi & 0xffff0000u);
    ulo = cvt2(v0 - f0, v1 - f1);
}
// ---- fp16 (score path) ----
__device__ __forceinline__ uint32_t cvt2h(float v0, float v1) {   // v0 -> low half
    uint32_t r;
    asm("cvt.rn.f16x2.f32 %0, %1, %2;" : "=r"(r) : "f"(v1), "f"(v0));
    return r;
}
__device__ __forceinline__ void split2h(float v0, float v1, uint32_t& uhi, uint32_t& ulo) {
    __half h0 = __float2half_rn(v0), h1 = __float2half_rn(v1);
    __half2 hh = __halves2half2(h0, h1);
    uhi = *(uint32_t*)&hh;
    ulo = cvt2h(v0 - __half2float(h0), v1 - __half2float(h1));
}
__device__ __forceinline__ void ldsm4(uint32_t* r, uint32_t addr) {
    asm volatile("ldmatrix.sync.aligned.m8n8.x4.shared.b16 {%0,%1,%2,%3}, [%4];"
        : "=r"(r[0]), "=r"(r[1]), "=r"(r[2]), "=r"(r[3]) : "r"(addr));
}
__device__ __forceinline__ void mma_bf16(float* d, const uint32_t* a,
                                         uint32_t b0, uint32_t b1) {
    asm volatile("mma.sync.aligned.m16n8k16.row.col.f32.bf16.bf16.f32 "
        "{%0,%1,%2,%3}, {%4,%5,%6,%7}, {%8,%9}, {%0,%1,%2,%3};"
        : "+f"(d[0]), "+f"(d[1]), "+f"(d[2]), "+f"(d[3])
        : "r"(a[0]), "r"(a[1]), "r"(a[2]), "r"(a[3]), "r"(b0), "r"(b1));
}
__device__ __forceinline__ void mma_f16(float* d, const uint32_t* a,
                                        uint32_t b0, uint32_t b1) {
    asm volatile("mma.sync.aligned.m16n8k16.row.col.f32.f16.f16.f32 "
        "{%0,%1,%2,%3}, {%4,%5,%6,%7}, {%8,%9}, {%0,%1,%2,%3};"
        : "+f"(d[0]), "+f"(d[1]), "+f"(d[2]), "+f"(d[3])
        : "r"(a[0]), "r"(a[1]), "r"(a[2]), "r"(a[3]), "r"(b0), "r"(b1));
}
// exp via 2^(x*log2e), deg-5 minimax poly (rel err ~3e-8), FMA-pipe only.
__device__ __forceinline__ float exp_poly(float x) {
    float t = x * 1.4426950408889634f;
    float fi = rintf(t);
    float f = t - fi;
    float p = 0.00133335581f;
    p = fmaf(p, f, 0.00961804886f);
    p = fmaf(p, f, 0.0555041087f);
    p = fmaf(p, f, 0.240226507f);
    p = fmaf(p, f, 0.69314718056f);
    p = fmaf(p, f, 1.0f);
    float s = __int_as_float(((int)fi + 127) << 23);
    return p * s;
}

// ---------------------------------------------------------------------------
// W prep (unchanged, bf16)
// ---------------------------------------------------------------------------
__global__ __launch_bounds__(256)
void wprep_kernel(const float* __restrict__ Wa, const float* __restrict__ Wc) {
    const int mode = blockIdx.x & 1, ks = blockIdx.x >> 1;
    const int h = threadIdx.x;
    const float* W = mode ? Wc : Wa;
    const int e0 = ks * 16;
    float v[16];
    #pragma unroll
    for (int j = 0; j < 16; j++)
        v[j] = (e0 + j < E_) ? W[h * E_ + e0 + j] : 0.f;
    #pragma unroll
    for (int i = 0; i < 8; i++) {
        uint32_t hi, lo;
        split2(v[2 * i], v[2 * i + 1], hi, lo);
        g_Wpk[mode][0][ks][h][i] = hi;
        g_Wpk[mode][1][ks][h][i] = lo;
    }
}

// ---------------------------------------------------------------------------
// Projection on bf16 HMMA (mainloop unchanged). Epilogue: mode 0 emits fp16
// A fragments; mode 1/2 emits fp32 g_projS.
// ---------------------------------------------------------------------------
#define PSTR 12

__global__ __launch_bounds__(256, 2)
void projmma_kernel(const float* __restrict__ Xa, const float* __restrict__ Xp,
                    const float* __restrict__ Xn,
                    const float* __restrict__ ba, const float* __restrict__ bc) {
    __shared__ uint32_t XH[64 * PSTR], XL[64 * PSTR];
    __shared__ uint32_t WH[256 * PSTR], WL[256 * PSTR];
    __shared__ float bias_s[256];

    const int tid = threadIdx.x, lane = tid & 31, w = tid >> 5;
    const int nq = blockIdx.x;
    const int mb = blockIdx.z;
    const int mode = mb >> 5, b = mb & 31;

    const float* X    = (mode == 0) ? Xa : (mode == 1 ? Xp : Xn);
    const float* bias = (mode == 0) ? ba : bc;
    const int    wsel = (mode == 0) ? 0 : 1;

    bias_s[tid] = bias[tid];

    const float* Xbase = X + ((size_t)b * N_ + nq * 64) * E_;
    const int warp_n = w & 3, warp_h = w >> 2;

    const uint32_t xhb = smem_u32(XH), xlb = smem_u32(XL);
    const uint32_t whb = smem_u32(WH), wlb = smem_u32(WL);

    const uint32_t a_off = (uint32_t)(warp_n * 16 + (lane & 15)) * 48 + ((lane >> 4) << 4);
    const uint32_t c_off = (uint32_t)((lane & 7) + ((lane >> 4) << 3)) * 48
                         + (((lane >> 3) & 1) << 4);

    const int fx_n = tid >> 2, fx_q = tid & 3;

    float acc[16][4];
    #pragma unroll
    for (int i = 0; i < 16; i++)
        #pragma unroll
        for (int j = 0; j < 4; j++) acc[i][j] = 0.f;

    for (int ks = 0; ks < KSTEPS; ks++) {
        const int e0 = ks * 16;
        __syncthreads();

        {
            float4 v = make_float4(0.f, 0.f, 0.f, 0.f);
            if (e0 + fx_q * 4 < E_)
                v = *(const float4*)(Xbase + fx_n * E_ + e0 + fx_q * 4);
            uint32_t h0, l0, h1, l1;
            split2(v.x, v.y, h0, l0);
            split2(v.z, v.w, h1, l1);
            const int o = fx_n * PSTR + fx_q * 2;
            XH[o] = h0; XH[o + 1] = h1;
            XL[o] = l0; XL[o + 1] = l1;
        }
        #pragma unroll
        for (int i = 0; i < 4; i++) {
            int idx = tid + i * 256;
            int var = idx >> 9, rem = idx & 511;
            int h = rem >> 1, half = rem & 1;
            uint4 v = *(const uint4*)&g_Wpk[wsel][var][ks][h][half * 4];
            uint32_t* dst = (var ? WL : WH) + h * PSTR + half * 4;
            *(uint4*)dst = v;
        }
        __syncthreads();

        uint32_t aH[4], aL[4];
        ldsm4(aH, xhb + a_off);
        ldsm4(aL, xlb + a_off);
        #pragma unroll
        for (int qh = 0; qh < 4; qh++) {
            const uint32_t hb = (uint32_t)(warp_h * 128 + qh * 32) * 48;
            uint32_t bh[8], bl[8];
            ldsm4(bh + 0, whb + hb + c_off);
            ldsm4(bh + 4, whb + hb + 16 * 48 + c_off);
            ldsm4(bl + 0, wlb + hb + c_off);
            ldsm4(bl + 4, wlb + hb + 16 * 48 + c_off);
            #pragma unroll
            for (int t2 = 0; t2 < 4; t2++) {
                const int ht = qh * 4 + t2;
                mma_bf16(acc[ht], aH, bh[2 * t2], bh[2 * t2 + 1]);
                mma_bf16(acc[ht], aL, bh[2 * t2], bh[2 * t2 + 1]);
                mma_bf16(acc[ht], aH, bl[2 * t2], bl[2 * t2 + 1]);
            }
        }
    }

    const int g = lane >> 2, q = lane & 3;
    if (mode == 0) {
        const int nt = nq * 4 + warp_n;
        #pragma unroll
        for (int ht2 = 0; ht2 < 8; ht2++) {
            const int ks = warp_h * 8 + ht2;
            const int he = 2 * ht2, ho = he + 1;
            const int hbe = warp_h * 128 + he * 8 + 2 * q;
            const int hbo = hbe + 8;
            uint32_t fh[4], fl[4];
            split2h(acc[he][0] + bias_s[hbe], acc[he][1] + bias_s[hbe + 1], fh[0], fl[0]);
            split2h(acc[he][2] + bias_s[hbe], acc[he][3] + bias_s[hbe + 1], fh[1], fl[1]);
            split2h(acc[ho][0] + bias_s[hbo], acc[ho][1] + bias_s[hbo + 1], fh[2], fl[2]);
            split2h(acc[ho][2] + bias_s[hbo], acc[ho][3] + bias_s[hbo + 1], fh[3], fl[3]);
            *(uint4*)&g_Apk[b][nt][ks][0][lane][0] = *(uint4*)fh;
            *(uint4*)&g_Apk[b][nt][ks][1][lane][0] = *(uint4*)fl;
        }
    } else {
        const int side = mode - 1;
        const int n0 = nq * 64 + warp_n * 16 + g;
        #pragma unroll
        for (int ht = 0; ht < 16; ht++) {
            const int h = warp_h * 128 + ht * 8 + 2 * q;
            const float b0 = bias_s[h], b1 = bias_s[h + 1];
            *(float2*)&g_projS[side][b][n0][h]     = make_float2(acc[ht][0] + b0, acc[ht][1] + b1);
            *(float2*)&g_projS[side][b][n0 + 8][h] = make_float2(acc[ht][2] + b0, acc[ht][3] + b1);
        }
    }
}

// ---------------------------------------------------------------------------
// Score: CTA = 256n x 64m of one (k, b, side). bx = k + 8*mq. 512 threads.
// fp16 2-pass: A = (aH + aL) exact fp16 pair, C = single fp16 of w*c.
// C built in 64h super-chunks (2 variants: S, F), double-buffered.
// ---------------------------------------------------------------------------
#define CSTR 36   // u32 row stride for 64h rows (144 B)
#define CB_VAR (64 * CSTR)                         // u32 per variant
#define SC_SMEM (2 * 2 * CB_VAR * 4 + 2048 + 256)  // ~39 KB

__global__ __launch_bounds__(512, 1)
void score_kernel(const float* __restrict__ W_att, const float* __restrict__ W_fc) {
    extern __shared__ uint32_t dsm[];
    // layout: Cb[2 buf][2 var][CB_VAR] | watt_s[256] | wfc_s[256] | rn[16] | rd[16]
    uint32_t* Cb = dsm;
    float* watt_s = (float*)(dsm + 2 * 2 * CB_VAR);
    float* wfc_s  = watt_s + 256;
    float* rn     = wfc_s + 256;
    float* rd     = rn + 16;

    const int tid  = threadIdx.x;
    const int lane = tid & 31, w = tid >> 5;   // w = 0..15 = n-tile
    const int k  = blockIdx.x & 7;
    const int mq = blockIdx.x >> 3;
    const int b = blockIdx.y, side = blockIdx.z;

    if (tid < H_) {
        watt_s[tid] = W_att[k * H_ + tid];
        wfc_s [tid] = W_fc [k * H_ + tid];
    }

    const float* Cs = &g_projS[side][b][0][0];
    const uint32_t cb_base = smem_u32(Cb);

    const uint32_t c_off = (uint32_t)((lane & 7) + ((lane >> 4) << 3)) * (CSTR * 4)
                         + (((lane >> 3) & 1) << 4);

    // C-build decomposition: thread -> m = tid>>3 (0..63), h-octet hq = tid&7
    const int cb_m = tid >> 3, cb_hq = tid & 7;
    const float* cb_src = Cs + (size_t)(mq * 64 + cb_m) * H_ + cb_hq * 8;
    const int cb_o = cb_m * CSTR + cb_hq * 4;

    float accS[2][4][4], accF[2][4][4];
    #pragma unroll
    for (int mh = 0; mh < 2; mh++)
        #pragma unroll
        for (int gg = 0; gg < 4; gg++)
            #pragma unroll
            for (int r = 0; r < 4; r++) { accS[mh][gg][r] = 0.f; accF[mh][gg][r] = 0.f; }

    __syncthreads();   // watt_s/wfc_s visible

    // ---- build(sc, buf): scale, cvt fp16, pack 64m x 64h x {S,F}
    #define BUILD(sc_, buf_) do {                                              \
        const float* s_ = cb_src + (sc_) * 64;                                 \
        const int hh_ = (sc_) * 64 + cb_hq * 8;                                \
        float4 v0 = *(const float4*)(s_);                                      \
        float4 v1 = *(const float4*)(s_ + 4);                                  \
        float4 wa0 = *(const float4*)(watt_s + hh_);                           \
        float4 wa1 = *(const float4*)(watt_s + hh_ + 4);                       \
        float4 wf0 = *(const float4*)(wfc_s + hh_);                            \
        float4 wf1 = *(const float4*)(wfc_s + hh_ + 4);                        \
        uint32_t* base_ = Cb + (buf_) * 2 * CB_VAR;                            \
        uint32_t p0 = cvt2h(wa0.x * v0.x, wa0.y * v0.y);                       \
        uint32_t p1 = cvt2h(wa0.z * v0.z, wa0.w * v0.w);                       \
        uint32_t p2 = cvt2h(wa1.x * v1.x, wa1.y * v1.y);                       \
        uint32_t p3 = cvt2h(wa1.z * v1.z, wa1.w * v1.w);                       \
        *(uint4*)&base_[cb_o] = make_uint4(p0, p1, p2, p3);                    \
        p0 = cvt2h(wf0.x * v0.x, wf0.y * v0.y);                                \
        p1 = cvt2h(wf0.z * v0.z, wf0.w * v0.w);                                \
        p2 = cvt2h(wf1.x * v1.x, wf1.y * v1.y);                                \
        p3 = cvt2h(wf1.z * v1.z, wf1.w * v1.w);                                \
        *(uint4*)&base_[CB_VAR + cb_o] = make_uint4(p0, p1, p2, p3);           \
    } while (0)

    BUILD(0, 0);
    __syncthreads();

    for (int sc = 0; sc < 4; sc++) {
        const int buf = sc & 1;
        if (sc < 3) BUILD(sc + 1, buf ^ 1);   // overlaps with mma below

        const uint32_t cSh = cb_base + (uint32_t)(buf * 2 + 0) * CB_VAR * 4;
        const uint32_t cFh = cb_base + (uint32_t)(buf * 2 + 1) * CB_VAR * 4;

        #pragma unroll
        for (int ksl = 0; ksl < 4; ksl++) {
            const int ksg = sc * 4 + ksl;
            uint32_t aH[4], aL[4];
            *(uint4*)aH = *(const uint4*)&g_Apk[b][w][ksg][0][lane][0];
            *(uint4*)aL = *(const uint4*)&g_Apk[b][w][ksg][1][lane][0];

            const uint32_t hkb = (uint32_t)(ksl * 32);
            #pragma unroll
            for (int mh = 0; mh < 2; mh++) {
                const uint32_t mrow = (uint32_t)(mh * 32) * (CSTR * 4);
                uint32_t c[8];
                // S
                ldsm4(c + 0, cSh + mrow + c_off + hkb);
                ldsm4(c + 4, cSh + mrow + 16 * CSTR * 4 + c_off + hkb);
                #pragma unroll
                for (int gg = 0; gg < 4; gg++) {
                    mma_f16(accS[mh][gg], aH, c[2*gg], c[2*gg+1]);
                    mma_f16(accS[mh][gg], aL, c[2*gg], c[2*gg+1]);
                }
                // F
                ldsm4(c + 0, cFh + mrow + c_off + hkb);
                ldsm4(c + 4, cFh + mrow + 16 * CSTR * 4 + c_off + hkb);
                #pragma unroll
                for (int gg = 0; gg < 4; gg++) {
                    mma_f16(accF[mh][gg], aH, c[2*gg], c[2*gg+1]);
                    mma_f16(accF[mh][gg], aL, c[2*gg], c[2*gg+1]);
                }
            }
        }
        __syncthreads();   // mma(sc) done; next iter may overwrite buf^1
    }

    // ---- epilogue: hybrid exp (even -> MUFU EX2, odd -> FMA-pipe poly)
    float num = 0.f, den = 0.f;
    #pragma unroll
    for (int mh = 0; mh < 2; mh++)
        #pragma unroll
        for (int gg = 0; gg < 4; gg++)
            #pragma unroll
            for (int r = 0; r < 4; r++) {
                float S = accS[mh][gg][r];
                float e = (r & 1) ? exp_poly(S) : __expf(S);
                den += e;
                num = fmaf(e, accF[mh][gg][r], num);
            }

    #pragma unroll
    for (int o = 16; o; o >>= 1) {
        num += __shfl_down_sync(0xffffffffu, num, o);
        den += __shfl_down_sync(0xffffffffu, den, o);
    }
    if (lane == 0) { rn[w] = num; rd[w] = den; }
    __syncthreads();
    if (tid == 0) {
        float sn = 0.f, sd = 0.f;
        #pragma unroll
        for (int q = 0; q < 16; q++) { sn += rn[q]; sd += rd[q]; }
        g_pnum[side][b][k][mq] = sn;
        g_pden[side][b][k][mq] = sd;
    }
}

// ---------------------------------------------------------------------------
// Finalize: loss = mean_b relu(score_n - score_p + margin). 256 threads.
// ---------------------------------------------------------------------------
__global__ void finalize_kernel(float* __restrict__ out) {
    __shared__ float sc[8][32];
    const int lane = threadIdx.x & 31;   // = b
    const int w    = threadIdx.x >> 5;
    float s = 0.f;
    #pragma unroll
    for (int pi = 0; pi < 2; pi++) {
        int p = w * 2 + pi;
        int side = p >> 3, k = p & 7;
        float n = 0.f, d = 0.f;
        #pragma unroll
        for (int q = 0; q < 4; q++) {
            n += g_pnum[side][lane][k][q];
            d += g_pden[side][lane][k][q];
        }
        float v = n / d;
        s += side ? v : -v;
    }
    sc[w][lane] = s;
    __syncthreads();
    if (w == 0) {
        float tot = 0.f;
        #pragma unroll
        for (int ww = 0; ww < 8; ww++) tot += sc[ww][lane];
        float v = fmaxf(tot + 0.2f, 0.f);
        #pragma unroll
        for (int o = 16; o; o >>= 1) v += __shfl_down_sync(0xffffffffu, v, o);
        if (lane == 0) out[0] = v * (1.0f / B_);
    }
}

// ---------------------------------------------------------------------------
extern "C" void kernel_launch(void* const* d_in, const int* in_sizes, int n_in,
                              void* d_out, int out_size) {
    const float* he_anchor = (const float*)d_in[0];
    const float* he_pos    = (const float*)d_in[1];
    const float* he_neg    = (const float*)d_in[2];
    const float* W_a2h     = (const float*)d_in[3];
    const float* b_a2h     = (const float*)d_in[4];
    const float* W_c2h     = (const float*)d_in[5];
    const float* b_c2h     = (const float*)d_in[6];
    const float* W_att     = (const float*)d_in[7];
    // d_in[8] = b_att : cancels in softmax
    const float* W_fc      = (const float*)d_in[9];
    // d_in[10] = b_fc : cancels in score difference

    cudaFuncSetAttribute(score_kernel,
                         cudaFuncAttributeMaxDynamicSharedMemorySize, SC_SMEM);

    wprep_kernel<<<2 * KSTEPS, 256>>>(W_a2h, W_c2h);

    projmma_kernel<<<dim3(4, 1, 96), 256>>>(he_anchor, he_pos, he_neg,
                                            b_a2h, b_c2h);

    score_kernel<<<dim3(32, B_, 2), 512, SC_SMEM>>>(W_att, W_fc);

    finalize_kernel<<<1, 256>>>((float*)d_out);
}